// round 14
// baseline (speedup 1.0000x reference)
#include <cuda_runtime.h>
#include <cuda_bf16.h>
#include <math.h>
#include <stdint.h>

#define N_NODES 30000
#define N_EDGES 480000
#define N_GRAPHS 64
#define AA 21
#define HID 128
#define D_IN 6165
#define C1V 149
#define C2V 298
#define C3V 596
#define FC1V 1024
#define OUTV 486

#define S596 600

// bf162 strides (pairs)
#define B149 76     // 152 channels
#define B298 152    // 304 channels

#define SPLITS 6
#define KSPLIT 1024

// ---------------- scratch ----------------
__device__ __nv_bfloat162 g_X0b[(size_t)N_NODES * B149];   // [f1(128)|f2(21)], pads 0
__device__ __nv_bfloat162 g_X1b[(size_t)N_NODES * B149];   // dinv-scaled conv1 out
__device__ __nv_bfloat162 g_X2b[(size_t)N_NODES * B298];   // dinv-scaled conv2 out
__device__ float g_X3[(size_t)N_NODES * S596];             // conv3 out (fp32)
__device__ __nv_bfloat16 g_AGGb[(size_t)N_NODES * 320];    // bf16 agg buffer (<=320 ch)
__device__ float g_part[(size_t)SPLITS * N_NODES * 128];
__device__ float g_dinv[N_NODES];
__device__ float g_invdeg[N_NODES];
__device__ int   g_cnt[N_NODES];
__device__ int   g_bsum[32];
__device__ int   g_rowptr[N_NODES + 1];
__device__ int   g_cursor[N_NODES];
__device__ int   g_col[N_EDGES];
__device__ float g_pool[N_GRAPHS * S596];
__device__ float g_fc1[N_GRAPHS * FC1V];

// f1 weights: tf32-preconverted fp32
__device__ float g_W1p[(size_t)6144 * 128 + 64];
// conv weights: bf16, TRANSPOSED [n][k], fully padded (zero)
__device__ __nv_bfloat16 g_Wc1pb[(size_t)256 * 160];
__device__ __nv_bfloat16 g_Wc2pb[(size_t)384 * 160];
__device__ __nv_bfloat16 g_Wc3pb[(size_t)640 * 320];

#define W1P_SZ  (6144 * 128)
#define PB1_SZ  (256 * 160)
#define PB2_SZ  (384 * 160)
#define PB3_SZ  (640 * 320)

// ---------------- fused pack + edge count ----------------
__device__ __forceinline__ float to_tf32(float v) {
    uint32_t t;
    asm("cvt.rna.tf32.f32 %0, %1;" : "=r"(t) : "f"(v));
    return __uint_as_float(t);
}

__global__ void k_prep(const float* __restrict__ W1, const float* __restrict__ Wc1,
                       const float* __restrict__ Wc2, const float* __restrict__ Wc3,
                       const int* __restrict__ dst) {
    int i = blockIdx.x * blockDim.x + threadIdx.x;
    if (i < W1P_SZ) {
        g_W1p[i] = to_tf32(W1[i]);
        return;
    }
    i -= W1P_SZ;
    if (i < PB1_SZ) {
        int n = i / 160, k = i % 160;
        // X0 layout is [f1(128)|f2(21)]; original Wc1 rows are [f2(21)|f1(128)]
        int ksrc = (k < 128) ? (AA + k) : ((k < C1V) ? (k - 128) : -1);
        float v = (ksrc >= 0 && n < C1V) ? Wc1[(size_t)ksrc * C1V + n] : 0.0f;
        g_Wc1pb[i] = __float2bfloat16(v);
        return;
    }
    i -= PB1_SZ;
    if (i < PB2_SZ) {
        int n = i / 160, k = i % 160;
        float v = (n < C2V && k < C1V) ? Wc2[(size_t)k * C2V + n] : 0.0f;
        g_Wc2pb[i] = __float2bfloat16(v);
        return;
    }
    i -= PB2_SZ;
    if (i < PB3_SZ) {
        int n = i / 320, k = i % 320;
        float v = (n < C3V && k < C2V) ? Wc3[(size_t)k * C3V + n] : 0.0f;
        g_Wc3pb[i] = __float2bfloat16(v);
        return;
    }
    i -= PB3_SZ;
    if (i < N_EDGES) atomicAdd(&g_cnt[dst[i]], 1);
}

// ---------------- parallel scan: phase 1 = per-block totals ----------------
__global__ void k_scan1() {
    __shared__ int ws[32];
    int t = threadIdx.x, lane = t & 31, w = t >> 5;
    int i = blockIdx.x * 1024 + t;
    int v = (i < N_NODES) ? g_cnt[i] : 0;
    int x = v;
#pragma unroll
    for (int off = 16; off > 0; off >>= 1)
        x += __shfl_down_sync(0xffffffffu, x, off);
    if (lane == 0) ws[w] = x;
    __syncthreads();
    if (w == 0) {
        int s = ws[lane];
#pragma unroll
        for (int off = 16; off > 0; off >>= 1)
            s += __shfl_down_sync(0xffffffffu, s, off);
        if (lane == 0) g_bsum[blockIdx.x] = s;
    }
}

// ---------------- parallel scan: phase 2 = base + local scan + node prep ------
__global__ void k_scan2() {
    __shared__ int warp_sums[32];
    __shared__ int s_base;
    int b = blockIdx.x;
    int t = threadIdx.x, lane = t & 31, w = t >> 5;
    if (t == 0) s_base = 0;
    __syncthreads();
    if (w == 0) {
        int bs = (lane < 30) ? g_bsum[lane] : 0;
#pragma unroll
        for (int off = 1; off < 32; off <<= 1) {
            int y = __shfl_up_sync(0xffffffffu, bs, off);
            if (lane >= off) bs += y;
        }
        if (b > 0 && lane == b - 1) s_base = bs;          // exclusive base
        if (b == 29 && lane == 29) g_rowptr[N_NODES] = bs; // grand total
    }
    __syncthreads();
    int base = s_base;

    int i = b * 1024 + t;
    int v = (i < N_NODES) ? g_cnt[i] : 0;
    if (i < N_NODES) g_cnt[i] = 0;
    int x = v;
#pragma unroll
    for (int off = 1; off < 32; off <<= 1) {
        int y = __shfl_up_sync(0xffffffffu, x, off);
        if (lane >= off) x += y;
    }
    if (lane == 31) warp_sums[w] = x;
    __syncthreads();
    if (w == 0) {
        int s = warp_sums[lane];
#pragma unroll
        for (int off = 1; off < 32; off <<= 1) {
            int y = __shfl_up_sync(0xffffffffu, s, off);
            if (lane >= off) s += y;
        }
        warp_sums[lane] = s;
    }
    __syncthreads();
    int warp_off = (w > 0) ? warp_sums[w - 1] : 0;
    if (i < N_NODES) {
        int excl = base + warp_off + x - v;
        g_rowptr[i] = excl;
        g_cursor[i] = excl;
        float deg = (float)v + 1.0f;
        g_dinv[i]   = rsqrtf(deg);
        g_invdeg[i] = 1.0f / deg;
    }
}

__global__ void k_fill(const int* __restrict__ src, const int* __restrict__ dst) {
    int e = blockIdx.x * blockDim.x + threadIdx.x;
    if (e < N_EDGES) {
        int p = atomicAdd(&g_cursor[dst[e]], 1);
        g_col[p] = src[e];
    }
}

// ---------------- helpers ----------------
__device__ __forceinline__ uint32_t smem_u32(const void* p) {
    return (uint32_t)__cvta_generic_to_shared(p);
}
__device__ __forceinline__ uint32_t pack_bf2(float x, float y) {
    __nv_bfloat162 t = __floats2bfloat162_rn(x, y);
    return *reinterpret_cast<uint32_t*>(&t);
}

// ---------------- fused split-K reduce + f2 ----------------
#define RED_BLOCKS 3750
__global__ void k_redf2(const float* __restrict__ b1, const float* __restrict__ px,
                        const float* __restrict__ W2, const float* __restrict__ b2) {
    if (blockIdx.x < RED_BLOCKS) {
        int idx = blockIdx.x * 256 + threadIdx.x;   // N_NODES*32
        if (idx >= N_NODES * 32) return;
        int i = idx >> 5, v = idx & 31;
        float4 s = make_float4(0.f, 0.f, 0.f, 0.f);
#pragma unroll
        for (int p = 0; p < SPLITS; p++) {
            const float4* pp = (const float4*)(g_part + (size_t)p * N_NODES * 128);
            float4 a = pp[idx];
            s.x += a.x; s.y += a.y; s.z += a.z; s.w += a.w;
        }
        float4 bb = ((const float4*)b1)[v];
        float r0 = fmaxf(s.x + bb.x, 0.0f);
        float r1 = fmaxf(s.y + bb.y, 0.0f);
        float r2 = fmaxf(s.z + bb.z, 0.0f);
        float r3 = fmaxf(s.w + bb.w, 0.0f);
        uint32_t* dst = (uint32_t*)(g_X0b + (size_t)i * B149 + v * 2);
        dst[0] = pack_bf2(r0, r1);
        dst[1] = pack_bf2(r2, r3);
    } else {
        int warp = ((blockIdx.x - RED_BLOCKS) * 256 + threadIdx.x) >> 5;
        int lane = threadIdx.x & 31;
        if (warp >= N_NODES) return;
        float x = 0.0f;
        if (lane < AA) x = px[(size_t)warp * D_IN + lane];
        float acc = (lane < AA) ? b2[lane] : 0.0f;
#pragma unroll
        for (int k = 0; k < AA; k++) {
            float xk = __shfl_sync(0xffffffffu, x, k);
            if (lane < AA) acc += xk * W2[k * AA + lane];
        }
        if (lane < AA) {
            __nv_bfloat16* p = (__nv_bfloat16*)g_X0b;
            p[(size_t)warp * 152 + 128 + lane] = __float2bfloat16(fmaxf(acc, 0.0f));
        }
    }
}

// ================= dedicated f1 GEMM (tf32, BM=128/BK=32, proven) =================
#define F1_STAGES 3
#define ASTR_F1 36

__device__ __forceinline__ void f1_load_stage(
    float (*As)[ASTR_F1], float (*Bs)[136],
    const float* __restrict__ A, const float* __restrict__ Bp,
    int bm, int k0, int M, int warp, int lane, int tid)
{
#pragma unroll
    for (int i = 0; i < 16; i++) {
        int r = warp * 16 + i;
        int gm = bm + r;
        int bytes = (gm < M) ? 4 : 0;
        uint32_t dsta = smem_u32(&As[r][lane]);
        const float* ga = A + (size_t)gm * D_IN + k0 + lane;
        asm volatile("cp.async.ca.shared.global [%0], [%1], 4, %2;\n"
                     :: "r"(dsta), "l"(ga), "r"(bytes));
    }
#pragma unroll
    for (int ii = 0; ii < 4; ii++) {
        int idx = ii * 256 + tid;
        int bk = idx >> 5;
        int c4 = (idx & 31) << 2;
        uint32_t dstb = smem_u32(&Bs[bk][c4]);
        const float* gb = Bp + (size_t)(k0 + bk) * 128 + c4;
        asm volatile("cp.async.cg.shared.global [%0], [%1], 16, %2;\n"
                     :: "r"(dstb), "l"(gb), "r"(16));
    }
}

__global__ __launch_bounds__(256, 2)
void k_f1(const float* __restrict__ A, const float* __restrict__ Bp,
          float* __restrict__ Cpart, int M) {
    extern __shared__ float sm[];
    float (*As)[128][ASTR_F1] = reinterpret_cast<float(*)[128][ASTR_F1]>(sm);
    float (*Bs)[32][136] = reinterpret_cast<float(*)[32][136]>(sm + F1_STAGES * 128 * ASTR_F1);

    int tid = threadIdx.x;
    int lane = tid & 31, warp = tid >> 5;
    int wm = warp & 3, wn = warp >> 2;
    int q = lane & 3, g = lane >> 2;
    int bm = blockIdx.x * 128;
    int kbeg = blockIdx.z * KSPLIT;
    float* C = Cpart + (size_t)blockIdx.z * N_NODES * 128;

    float acc[2][8][4];
#pragma unroll
    for (int i = 0; i < 2; i++)
#pragma unroll
        for (int j = 0; j < 8; j++)
#pragma unroll
            for (int r = 0; r < 4; r++) acc[i][j][r] = 0.0f;

    const int T = KSPLIT / 32;

#pragma unroll
    for (int s = 0; s < F1_STAGES - 1; s++) {
        f1_load_stage(As[s], Bs[s], A, Bp, bm, kbeg + s * 32, M, warp, lane, tid);
        asm volatile("cp.async.commit_group;\n");
    }

    for (int t = 0; t < T; t++) {
        int nxt = t + F1_STAGES - 1;
        if (nxt < T) {
            int slot = nxt % F1_STAGES;
            f1_load_stage(As[slot], Bs[slot], A, Bp, bm, kbeg + nxt * 32, M, warp, lane, tid);
        }
        asm volatile("cp.async.commit_group;\n");
        asm volatile("cp.async.wait_group %0;\n" :: "n"(F1_STAGES - 1));
        __syncthreads();

        int cur = t % F1_STAGES;
#pragma unroll
        for (int sp = 0; sp < 4; sp++) {
            int s8 = sp * 8;
            uint32_t a[2][4];
#pragma unroll
            for (int i = 0; i < 2; i++) {
                int m = wm * 32 + i * 16 + g;
                a[i][0] = __float_as_uint(As[cur][m][s8 + q]);
                a[i][1] = __float_as_uint(As[cur][m + 8][s8 + q]);
                a[i][2] = __float_as_uint(As[cur][m][s8 + q + 4]);
                a[i][3] = __float_as_uint(As[cur][m + 8][s8 + q + 4]);
            }
            uint32_t b[8][2];
#pragma unroll
            for (int j = 0; j < 8; j++) {
                int n = wn * 64 + j * 8 + g;
                b[j][0] = __float_as_uint(Bs[cur][s8 + q][n]);
                b[j][1] = __float_as_uint(Bs[cur][s8 + q + 4][n]);
            }
#pragma unroll
            for (int i = 0; i < 2; i++)
#pragma unroll
                for (int j = 0; j < 8; j++) {
                    asm volatile(
                        "mma.sync.aligned.m16n8k8.row.col.f32.tf32.tf32.f32 "
                        "{%0,%1,%2,%3}, {%4,%5,%6,%7}, {%8,%9}, {%0,%1,%2,%3};\n"
                        : "+f"(acc[i][j][0]), "+f"(acc[i][j][1]),
                          "+f"(acc[i][j][2]), "+f"(acc[i][j][3])
                        : "r"(a[i][0]), "r"(a[i][1]), "r"(a[i][2]), "r"(a[i][3]),
                          "r"(b[j][0]), "r"(b[j][1]));
                }
        }
        __syncthreads();
    }

#pragma unroll
    for (int i = 0; i < 2; i++) {
        int row0 = bm + wm * 32 + i * 16 + g;
#pragma unroll
        for (int j = 0; j < 8; j++) {
            int col0 = wn * 64 + j * 8 + 2 * q;
            if (row0 < M) {
                C[(size_t)row0 * 128 + col0]     = acc[i][j][0];
                C[(size_t)row0 * 128 + col0 + 1] = acc[i][j][1];
            }
            if (row0 + 8 < M) {
                C[(size_t)(row0 + 8) * 128 + col0]     = acc[i][j][2];
                C[(size_t)(row0 + 8) * 128 + col0 + 1] = acc[i][j][3];
            }
        }
    }
}

// ================= bf16 conv GEMM: m16n8k16, BK=32, 3 stages =================
#define CSTAGE 3

__device__ __forceinline__ void load_stage_b16(
    uint32_t (*As)[20], uint32_t (*Bs)[20],
    const uint4* __restrict__ A4, int ldA4,
    const uint4* __restrict__ B4, int ldB4,
    int bm, int bn, int M, int k0, int tid)
{
    int kq = k0 >> 3;
#pragma unroll
    for (int p = 0; p < 2; p++) {
        int idx = p * 256 + tid;
        int r = idx >> 2, c = idx & 3;
        int gm = bm + r;
        int bytes = (gm < M) ? 16 : 0;
        uint32_t dsta = smem_u32(&As[r][c * 4]);
        const uint4* ga = A4 + (size_t)gm * ldA4 + kq + c;
        asm volatile("cp.async.cg.shared.global [%0], [%1], 16, %2;\n"
                     :: "r"(dsta), "l"(ga), "r"(bytes));
    }
#pragma unroll
    for (int p = 0; p < 2; p++) {
        int idx = p * 256 + tid;
        int r = idx >> 2, c = idx & 3;
        uint32_t dstb = smem_u32(&Bs[r][c * 4]);
        const uint4* gb = B4 + (size_t)(bn + r) * ldB4 + kq + c;
        asm volatile("cp.async.cg.shared.global [%0], [%1], 16, %2;\n"
                     :: "r"(dstb), "l"(gb), "r"(16));
    }
}

__global__ __launch_bounds__(256, 2)
void k_mmab(const uint4* __restrict__ A4, int ldA4,
            const uint4* __restrict__ B4, int ldB4,
            float* __restrict__ C, int ldc,
            __nv_bfloat162* __restrict__ Cb, int ldcb,
            const float* __restrict__ bias,
            const float* __restrict__ rowscale,
            int M, int Kp, int N) {
    extern __shared__ uint32_t smu[];
    uint32_t (*As)[128][20] = reinterpret_cast<uint32_t(*)[128][20]>(smu);
    uint32_t (*Bs)[128][20] = reinterpret_cast<uint32_t(*)[128][20]>(smu + CSTAGE * 128 * 20);

    int tid = threadIdx.x;
    int lane = tid & 31, warp = tid >> 5;
    int wm = warp & 3, wn = warp >> 2;
    int q = lane & 3, g = lane >> 2;
    int bm = blockIdx.x * 128;
    int bn = blockIdx.y * 128;

    float acc[2][8][4];
#pragma unroll
    for (int i = 0; i < 2; i++)
#pragma unroll
        for (int j = 0; j < 8; j++)
#pragma unroll
            for (int r = 0; r < 4; r++) acc[i][j][r] = 0.0f;

    const int T = Kp >> 5;

#pragma unroll
    for (int s = 0; s < CSTAGE - 1; s++) {
        if (s < T)
            load_stage_b16(As[s], Bs[s], A4, ldA4, B4, ldB4, bm, bn, M, s << 5, tid);
        asm volatile("cp.async.commit_group;\n");
    }

    for (int t = 0; t < T; t++) {
        int nxt = t + CSTAGE - 1;
        if (nxt < T) {
            int slot = nxt % CSTAGE;
            load_stage_b16(As[slot], Bs[slot], A4, ldA4, B4, ldB4, bm, bn, M, nxt << 5, tid);
        }
        asm volatile("cp.async.commit_group;\n");
        asm volatile("cp.async.wait_group %0;\n" :: "n"(CSTAGE - 1));
        __syncthreads();

        int cur = t % CSTAGE;
#pragma unroll
        for (int s = 0; s < 2; s++) {
            int h = s * 8;
            uint32_t a[2][4];
#pragma unroll
            for (int i = 0; i < 2; i++) {
                int m = wm * 32 + i * 16 + g;
                a[i][0] = As[cur][m][h + q];
                a[i][1] = As[cur][m + 8][h + q];
                a[i][2] = As[cur][m][h + q + 4];
                a[i][3] = As[cur][m + 8][h + q + 4];
            }
#pragma unroll
            for (int j = 0; j < 8; j++) {
                int n = wn * 64 + j * 8 + g;
                uint32_t b0 = Bs[cur][n][h + q];
                uint32_t b1 = Bs[cur][n][h + q + 4];
#pragma unroll
                for (int i = 0; i < 2; i++) {
                    asm volatile(
                        "mma.sync.aligned.m16n8k16.row.col.f32.bf16.bf16.f32 "
                        "{%0,%1,%2,%3}, {%4,%5,%6,%7}, {%8,%9}, {%0,%1,%2,%3};\n"
                        : "+f"(acc[i][j][0]), "+f"(acc[i][j][1]),
                          "+f"(acc[i][j][2]), "+f"(acc[i][j][3])
                        : "r"(a[i][0]), "r"(a[i][1]), "r"(a[i][2]), "r"(a[i][3]),
                          "r"(b0), "r"(b1));
                }
            }
        }
        __syncthreads();
    }

#pragma unroll
    for (int i = 0; i < 2; i++) {
        int row0 = bm + wm * 32 + i * 16 + g;
        float sc0 = 1.0f, sc1 = 1.0f;
        if (rowscale) {
            if (row0 < M)     sc0 = __ldg(&rowscale[row0]);
            if (row0 + 8 < M) sc1 = __ldg(&rowscale[row0 + 8]);
        }
#pragma unroll
        for (int j = 0; j < 8; j++) {
            int col0 = bn + wn * 64 + j * 8 + 2 * q;
            float bz0 = (col0 < N) ? __ldg(&bias[col0]) : 0.0f;
            float bz1 = (col0 + 1 < N) ? __ldg(&bias[col0 + 1]) : 0.0f;
            float v00 = sc0 * fmaxf(acc[i][j][0] + bz0, 0.0f);
            float v01 = sc0 * fmaxf(acc[i][j][1] + bz1, 0.0f);
            float v10 = sc1 * fmaxf(acc[i][j][2] + bz0, 0.0f);
            float v11 = sc1 * fmaxf(acc[i][j][3] + bz1, 0.0f);
            if (Cb) {
                bool c1ok = (col0 + 1 < N);
                if (row0 < M && col0 < N)
                    Cb[(size_t)row0 * ldcb + (col0 >> 1)] =
                        __floats2bfloat162_rn(v00, c1ok ? v01 : 0.0f);
                if (row0 + 8 < M && col0 < N)
                    Cb[(size_t)(row0 + 8) * ldcb + (col0 >> 1)] =
                        __floats2bfloat162_rn(v10, c1ok ? v11 : 0.0f);
            } else {
                if (row0 < M) {
                    if (col0 < N)     C[(size_t)row0 * ldc + col0]     = v00;
                    if (col0 + 1 < N) C[(size_t)row0 * ldc + col0 + 1] = v01;
                }
                if (row0 + 8 < M) {
                    if (col0 < N)     C[(size_t)(row0 + 8) * ldc + col0]     = v10;
                    if (col0 + 1 < N) C[(size_t)(row0 + 8) * ldc + col0 + 1] = v11;
                }
            }
        }
    }
}

// ---------------- bf16 gather aggregation -> bf16 AGG ----------------
__device__ __forceinline__ void accum8(float* acc, float d, uint4 v) {
    const __nv_bfloat162* p = (const __nv_bfloat162*)&v;
#pragma unroll
    for (int k = 0; k < 4; k++) {
        float2 f = __bfloat1622float2(p[k]);
        acc[2 * k]     += d * f.x;
        acc[2 * k + 1] += d * f.y;
    }
}
__device__ __forceinline__ void accum8_1(float* acc, uint4 v) {
    const __nv_bfloat162* p = (const __nv_bfloat162*)&v;
#pragma unroll
    for (int k = 0; k < 4; k++) {
        float2 f = __bfloat1622float2(p[k]);
        acc[2 * k]     += f.x;
        acc[2 * k + 1] += f.y;
    }
}

// conv1 input (unscaled X0b): OUT_i = dinv_i * sum dinv_j X_j + invdeg_i X_i
template<int NPB>
__global__ void k_aggb_old(const uint4* __restrict__ X, int ldx,
                           uint4* __restrict__ OUT, int ldo, int dataW) {
    int i = blockIdx.x * NPB + threadIdx.y;
    if (i >= N_NODES) return;
    int c = threadIdx.x;
    uint4* orow = OUT + (size_t)i * ldo;
    if (c >= dataW) {
        orow[c] = make_uint4(0u, 0u, 0u, 0u);
        return;
    }
    int beg = g_rowptr[i], end = g_rowptr[i + 1];
    float acc[8] = {0.f, 0.f, 0.f, 0.f, 0.f, 0.f, 0.f, 0.f};
    int e = beg;
    for (; e + 4 <= end; e += 4) {
        int j0 = g_col[e], j1 = g_col[e + 1], j2 = g_col[e + 2], j3 = g_col[e + 3];
        float d0 = g_dinv[j0], d1 = g_dinv[j1], d2 = g_dinv[j2], d3 = g_dinv[j3];
        uint4 v0 = X[(size_t)j0 * ldx + c];
        uint4 v1 = X[(size_t)j1 * ldx + c];
        uint4 v2 = X[(size_t)j2 * ldx + c];
        uint4 v3 = X[(size_t)j3 * ldx + c];
        accum8(acc, d0, v0); accum8(acc, d1, v1); accum8(acc, d2, v2); accum8(acc, d3, v3);
    }
    for (; e < end; e++) {
        int j = g_col[e];
        accum8(acc, g_dinv[j], X[(size_t)j * ldx + c]);
    }
    float di = g_dinv[i], vi = g_invdeg[i];
    float self[8] = {0.f, 0.f, 0.f, 0.f, 0.f, 0.f, 0.f, 0.f};
    accum8_1(self, X[(size_t)i * ldx + c]);
    uint4 o;
    o.x = pack_bf2(di * acc[0] + vi * self[0], di * acc[1] + vi * self[1]);
    o.y = pack_bf2(di * acc[2] + vi * self[2], di * acc[3] + vi * self[3]);
    o.z = pack_bf2(di * acc[4] + vi * self[4], di * acc[5] + vi * self[5]);
    o.w = pack_bf2(di * acc[6] + vi * self[6], di * acc[7] + vi * self[7]);
    orow[c] = o;
}

// scaled input Xs = dinv .* x : OUT_i = dinv_i * (Xs_i + sum Xs_j)
template<int NPB>
__global__ void k_aggb_s(const uint4* __restrict__ X, int ldx,
                         uint4* __restrict__ OUT, int ldo, int dataW) {
    int i = blockIdx.x * NPB + threadIdx.y;
    if (i >= N_NODES) return;
    int c = threadIdx.x;
    uint4* orow = OUT + (size_t)i * ldo;
    if (c >= dataW) {
        orow[c] = make_uint4(0u, 0u, 0u, 0u);
        return;
    }
    int beg = g_rowptr[i], end = g_rowptr[i + 1];
    float acc[8] = {0.f, 0.f, 0.f, 0.f, 0.f, 0.f, 0.f, 0.f};
    accum8_1(acc, X[(size_t)i * ldx + c]);
    int e = beg;
    for (; e + 4 <= end; e += 4) {
        int j0 = g_col[e], j1 = g_col[e + 1], j2 = g_col[e + 2], j3 = g_col[e + 3];
        uint4 v0 = X[(size_t)j0 * ldx + c];
        uint4 v1 = X[(size_t)j1 * ldx + c];
        uint4 v2 = X[(size_t)j2 * ldx + c];
        uint4 v3 = X[(size_t)j3 * ldx + c];
        accum8_1(acc, v0); accum8_1(acc, v1); accum8_1(acc, v2); accum8_1(acc, v3);
    }
    for (; e < end; e++) accum8_1(acc, X[(size_t)g_col[e] * ldx + c]);
    float di = g_dinv[i];
    uint4 o;
    o.x = pack_bf2(di * acc[0], di * acc[1]);
    o.y = pack_bf2(di * acc[2], di * acc[3]);
    o.z = pack_bf2(di * acc[4], di * acc[5]);
    o.w = pack_bf2(di * acc[6], di * acc[7]);
    orow[c] = o;
}

// ---------------- global mean pool (float4, X3 fp32) ----------------
__device__ __forceinline__ void add4(float4& s, float4 x) {
    s.x += x.x; s.y += x.y; s.z += x.z; s.w += x.w;
}
__device__ __forceinline__ int lower_bound_i(const int* a, int n, int v) {
    int lo = 0, hi = n;
    while (lo < hi) { int m = (lo + hi) >> 1; if (a[m] < v) lo = m + 1; else hi = m; }
    return lo;
}

__global__ void k_pool4(const int* __restrict__ batch) {
    int gq = blockIdx.x;
    __shared__ int s_beg, s_end;
    if (threadIdx.x == 0) {
        s_beg = lower_bound_i(batch, N_NODES, gq);
        s_end = lower_bound_i(batch, N_NODES, gq + 1);
    }
    __syncthreads();
    int c = threadIdx.x;
    if (c >= 150) return;
    const float4* X4 = (const float4*)g_X3;
    int beg = s_beg, end = s_end;
    float4 s = make_float4(0.f, 0.f, 0.f, 0.f);
    int n = beg;
    for (; n + 4 <= end; n += 4) {
        float4 x0 = X4[(size_t)n * 150 + c];
        float4 x1 = X4[(size_t)(n + 1) * 150 + c];
        float4 x2 = X4[(size_t)(n + 2) * 150 + c];
        float4 x3 = X4[(size_t)(n + 3) * 150 + c];
        add4(s, x0); add4(s, x1); add4(s, x2); add4(s, x3);
    }
    for (; n < end; n++) add4(s, X4[(size_t)n * 150 + c]);
    float inv = 1.0f / fmaxf((float)(end - beg), 1.0f);
    float4 r;
    r.x = s.x * inv; r.y = s.y * inv; r.z = s.z * inv; r.w = s.w * inv;
    ((float4*)g_pool)[(size_t)gq * 150 + c] = r;
}

// ---------------- FC head: tiled GEMM-style (weights read once per col-tile) ----
// fc1: grid (8 col-tiles of 128, 8 graph-tiles of 8), 128 thr
__global__ void k_fc1g(const float* __restrict__ Wg1, const float* __restrict__ bg1,
                       const float* __restrict__ gamma, const float* __restrict__ beta) {
    __shared__ float sp[8][C3V];
    int gb = blockIdx.y;
    int o = blockIdx.x * 128 + threadIdx.x;
    for (int idx = threadIdx.x; idx < 8 * C3V; idx += 128) {
        int g = idx / C3V, k = idx - g * C3V;
        sp[g][k] = g_pool[(size_t)(gb * 8 + g) * S596 + k];
    }
    __syncthreads();
    float acc[8];
    float bz = bg1[o];
#pragma unroll
    for (int g = 0; g < 8; g++) acc[g] = bz;
    for (int k = 0; k < C3V; k++) {
        float wv = Wg1[(size_t)k * FC1V + o];
#pragma unroll
        for (int g = 0; g < 8; g++) acc[g] += sp[g][k] * wv;
    }
    float inv = 1.0f / sqrtf(1.0f + 1e-5f);
    float ga = gamma[o], be = beta[o];
#pragma unroll
    for (int g = 0; g < 8; g++) {
        float v = fmaxf(ga * (acc[g] * inv) + be, 0.0f);
        g_fc1[(size_t)(gb * 8 + g) * FC1V + o] = v;
    }
}

// fc2: grid (4 col-tiles of 128, 8 graph-tiles of 8), 128 thr
__global__ void k_fc2g(const float* __restrict__ Wg2, const float* __restrict__ bg2,
                       float* __restrict__ out) {
    __shared__ float sx[8][FC1V];
    int gb = blockIdx.y;
    int o = blockIdx.x * 128 + threadIdx.x;
    for (int idx = threadIdx.x; idx < 8 * FC1V; idx += 128) {
        int g = idx >> 10, k = idx & 1023;
        sx[g][k] = g_fc1[(size_t)(gb * 8 + g) * FC1V + k];
    }
    __syncthreads();
    if (o >= OUTV) return;
    float acc[8];
    float bz = bg2[o];
#pragma unroll
    for (int g = 0; g < 8; g++) acc[g] = bz;
    for (int k = 0; k < FC1V; k++) {
        float wv = Wg2[(size_t)k * OUTV + o];
#pragma unroll
        for (int g = 0; g < 8; g++) acc[g] += sx[g][k] * wv;
    }
#pragma unroll
    for (int g = 0; g < 8; g++)
        out[(size_t)(gb * 8 + g) * OUTV + o] = 1.0f / (1.0f + expf(-acc[g]));
}

// ---------------- launch ----------------
extern "C" void kernel_launch(void* const* d_in, const int* in_sizes, int n_in,
                              void* d_out, int out_size) {
    const float* prot_x = (const float*)d_in[0];
    const int*   src    = (const int*)d_in[1];
    const int*   dst    = (const int*)d_in[2];
    const int*   batch  = (const int*)d_in[3];
    const float* W1  = (const float*)d_in[4];
    const float* b1  = (const float*)d_in[5];
    const float* W2  = (const float*)d_in[6];
    const float* b2  = (const float*)d_in[7];
    const float* Wc1 = (const float*)d_in[8];
    const float* bc1 = (const float*)d_in[9];
    const float* Wc2 = (const float*)d_in[10];
    const float* bc2 = (const float*)d_in[11];
    const float* Wc3 = (const float*)d_in[12];
    const float* bc3 = (const float*)d_in[13];
    const float* Wg1 = (const float*)d_in[14];
    const float* bg1 = (const float*)d_in[15];
    const float* Wg2 = (const float*)d_in[16];
    const float* bg2 = (const float*)d_in[17];
    const float* gamma = (const float*)d_in[18];
    const float* beta  = (const float*)d_in[19];

    float *X3, *PART, *W1p, *dinv;
    __nv_bfloat162 *X0b, *X1b, *X2b;
    __nv_bfloat16 *AGGb, *W1b, *W2b2, *W3b;
    cudaGetSymbolAddress((void**)&X0b, g_X0b);
    cudaGetSymbolAddress((void**)&X1b, g_X1b);
    cudaGetSymbolAddress((void**)&X2b, g_X2b);
    cudaGetSymbolAddress((void**)&X3, g_X3);
    cudaGetSymbolAddress((void**)&AGGb, g_AGGb);
    cudaGetSymbolAddress((void**)&PART, g_part);
    cudaGetSymbolAddress((void**)&W1p, g_W1p);
    cudaGetSymbolAddress((void**)&W1b, g_Wc1pb);
    cudaGetSymbolAddress((void**)&W2b2, g_Wc2pb);
    cudaGetSymbolAddress((void**)&W3b, g_Wc3pb);
    cudaGetSymbolAddress((void**)&dinv, g_dinv);

    const int SMF1 = F1_STAGES * (128 * ASTR_F1 + 32 * 136) * 4;  // 107520
    const int SMC  = CSTAGE * 2 * 128 * 20 * 4;                   // 61440
    cudaFuncSetAttribute(k_f1,   cudaFuncAttributeMaxDynamicSharedMemorySize, SMF1);
    cudaFuncSetAttribute(k_mmab, cudaFuncAttributeMaxDynamicSharedMemorySize, SMC);

    const int PREP_TOTAL = W1P_SZ + PB1_SZ + PB2_SZ + PB3_SZ + N_EDGES;

    // 1-3: fused pack+count, parallel scan (2 phases)
    k_prep<<<(PREP_TOTAL + 255) / 256, 256>>>(W1, Wc1, Wc2, Wc3, dst);
    k_scan1<<<30, 1024>>>();
    k_scan2<<<30, 1024>>>();

    // 4: f1 GEMM (profiler window slot)
    k_f1<<<dim3(235, 1, SPLITS), 256, SMF1>>>(prot_x + AA, W1p, PART, N_NODES);

    // 5-6: CSR fill, fused reduce + f2 -> X0b
    k_fill<<<(N_EDGES + 255) / 256, 256>>>(src, dst);
    k_redf2<<<RED_BLOCKS * 2, 256>>>(b1, prot_x, W2, b2);

    // conv1: agg (unscaled X0b) -> bf16 AGGb(ld 20 u4); bf16 GEMM -> X1b (dinv-scaled)
    k_aggb_old<12><<<(N_NODES + 11) / 12, dim3(20, 12)>>>(
        (const uint4*)X0b, 19, (uint4*)AGGb, 20, 19);
    k_mmab<<<dim3(235, 2), 256, SMC>>>((const uint4*)AGGb, 20, (const uint4*)W1b, 20,
                                       nullptr, 0, X1b, B149,
                                       bc1, dinv, N_NODES, 160, C1V);
    // conv2
    k_aggb_s<12><<<(N_NODES + 11) / 12, dim3(20, 12)>>>(
        (const uint4*)X1b, 19, (uint4*)AGGb, 20, 19);
    k_mmab<<<dim3(235, 3), 256, SMC>>>((const uint4*)AGGb, 20, (const uint4*)W2b2, 20,
                                       nullptr, 0, X2b, B298,
                                       bc2, dinv, N_NODES, 160, C2V);
    // conv3 -> fp32 X3
    k_aggb_s<6><<<(N_NODES + 5) / 6, dim3(40, 6)>>>(
        (const uint4*)X2b, 38, (uint4*)AGGb, 40, 38);
    k_mmab<<<dim3(235, 5), 256, SMC>>>((const uint4*)AGGb, 40, (const uint4*)W3b, 40,
                                       X3, S596, nullptr, 0,
                                       bc3, nullptr, N_NODES, 320, C3V);

    // pool + tiled FC head
    k_pool4<<<N_GRAPHS, 160>>>(batch);
    k_fc1g<<<dim3(8, 8), 128>>>(Wg1, bg1, gamma, beta);
    k_fc2g<<<dim3(4, 8), 128>>>(Wg2, bg2, (float*)d_out);
}

// round 15
// speedup vs baseline: 1.1837x; 1.1837x over previous
#include <cuda_runtime.h>
#include <cuda_bf16.h>
#include <math.h>
#include <stdint.h>

#define N_NODES 30000
#define N_EDGES 480000
#define N_GRAPHS 64
#define AA 21
#define HID 128
#define D_IN 6165
#define C1V 149
#define C2V 298
#define C3V 596
#define FC1V 1024
#define OUTV 486

#define S596 600

// bf162 strides (pairs)
#define B149 76     // 152 channels
#define B298 152    // 304 channels

#define SPLITS 6
#define KSPLIT 1024

// ---------------- scratch ----------------
__device__ __nv_bfloat162 g_X0b[(size_t)N_NODES * B149];   // [f1(128)|f2(21)], pads 0
__device__ __nv_bfloat162 g_X1b[(size_t)N_NODES * B149];   // dinv-scaled conv1 out
__device__ __nv_bfloat162 g_X2b[(size_t)N_NODES * B298];   // dinv-scaled conv2 out
__device__ float g_X3[(size_t)N_NODES * S596];             // conv3 out (fp32)
__device__ __nv_bfloat16 g_AGGb[(size_t)N_NODES * 320];    // bf16 agg buffer (<=320 ch)
__device__ float g_part[(size_t)SPLITS * N_NODES * 128];
__device__ float g_dinv[N_NODES];
__device__ float g_invdeg[N_NODES];
__device__ int   g_cnt[N_NODES];
__device__ int   g_bsum[32];
__device__ int   g_rowptr[N_NODES + 1];
__device__ int   g_cursor[N_NODES];
__device__ int   g_col[N_EDGES];
__device__ float g_pool[N_GRAPHS * S596];
__device__ float g_fc1[N_GRAPHS * FC1V];

// f1 weights: tf32-preconverted fp32
__device__ float g_W1p[(size_t)6144 * 128 + 64];
// conv weights: bf16, TRANSPOSED [n][k], fully padded (zero)
__device__ __nv_bfloat16 g_Wc1pb[(size_t)256 * 160];
__device__ __nv_bfloat16 g_Wc2pb[(size_t)384 * 160];
__device__ __nv_bfloat16 g_Wc3pb[(size_t)640 * 320];

#define W1P_SZ  (6144 * 128)
#define PB1_SZ  (256 * 160)
#define PB2_SZ  (384 * 160)
#define PB3_SZ  (640 * 320)

// ---------------- fused pack + edge count ----------------
__device__ __forceinline__ float to_tf32(float v) {
    uint32_t t;
    asm("cvt.rna.tf32.f32 %0, %1;" : "=r"(t) : "f"(v));
    return __uint_as_float(t);
}

__global__ void k_prep(const float* __restrict__ W1, const float* __restrict__ Wc1,
                       const float* __restrict__ Wc2, const float* __restrict__ Wc3,
                       const int* __restrict__ dst) {
    int i = blockIdx.x * blockDim.x + threadIdx.x;
    if (i < W1P_SZ) {
        g_W1p[i] = to_tf32(W1[i]);
        return;
    }
    i -= W1P_SZ;
    if (i < PB1_SZ) {
        int n = i / 160, k = i % 160;
        // X0 layout is [f1(128)|f2(21)]; original Wc1 rows are [f2(21)|f1(128)]
        int ksrc = (k < 128) ? (AA + k) : ((k < C1V) ? (k - 128) : -1);
        float v = (ksrc >= 0 && n < C1V) ? Wc1[(size_t)ksrc * C1V + n] : 0.0f;
        g_Wc1pb[i] = __float2bfloat16(v);
        return;
    }
    i -= PB1_SZ;
    if (i < PB2_SZ) {
        int n = i / 160, k = i % 160;
        float v = (n < C2V && k < C1V) ? Wc2[(size_t)k * C2V + n] : 0.0f;
        g_Wc2pb[i] = __float2bfloat16(v);
        return;
    }
    i -= PB2_SZ;
    if (i < PB3_SZ) {
        int n = i / 320, k = i % 320;
        float v = (n < C3V && k < C2V) ? Wc3[(size_t)k * C3V + n] : 0.0f;
        g_Wc3pb[i] = __float2bfloat16(v);
        return;
    }
    i -= PB3_SZ;
    if (i < N_EDGES) atomicAdd(&g_cnt[dst[i]], 1);
}

// ---------------- parallel scan: phase 1 = per-block totals ----------------
__global__ void k_scan1() {
    __shared__ int ws[32];
    int t = threadIdx.x, lane = t & 31, w = t >> 5;
    int i = blockIdx.x * 1024 + t;
    int v = (i < N_NODES) ? g_cnt[i] : 0;
    int x = v;
#pragma unroll
    for (int off = 16; off > 0; off >>= 1)
        x += __shfl_down_sync(0xffffffffu, x, off);
    if (lane == 0) ws[w] = x;
    __syncthreads();
    if (w == 0) {
        int s = ws[lane];
#pragma unroll
        for (int off = 16; off > 0; off >>= 1)
            s += __shfl_down_sync(0xffffffffu, s, off);
        if (lane == 0) g_bsum[blockIdx.x] = s;
    }
}

// ---------------- parallel scan: phase 2 = base + local scan + node prep ------
__global__ void k_scan2() {
    __shared__ int warp_sums[32];
    __shared__ int s_base;
    int b = blockIdx.x;
    int t = threadIdx.x, lane = t & 31, w = t >> 5;
    if (t == 0) s_base = 0;
    __syncthreads();
    if (w == 0) {
        int bs = (lane < 30) ? g_bsum[lane] : 0;
#pragma unroll
        for (int off = 1; off < 32; off <<= 1) {
            int y = __shfl_up_sync(0xffffffffu, bs, off);
            if (lane >= off) bs += y;
        }
        if (b > 0 && lane == b - 1) s_base = bs;           // exclusive base
        if (b == 29 && lane == 29) g_rowptr[N_NODES] = bs; // grand total
    }
    __syncthreads();
    int base = s_base;

    int i = b * 1024 + t;
    int v = (i < N_NODES) ? g_cnt[i] : 0;
    if (i < N_NODES) g_cnt[i] = 0;
    int x = v;
#pragma unroll
    for (int off = 1; off < 32; off <<= 1) {
        int y = __shfl_up_sync(0xffffffffu, x, off);
        if (lane >= off) x += y;
    }
    if (lane == 31) warp_sums[w] = x;
    __syncthreads();
    if (w == 0) {
        int s = warp_sums[lane];
#pragma unroll
        for (int off = 1; off < 32; off <<= 1) {
            int y = __shfl_up_sync(0xffffffffu, s, off);
            if (lane >= off) s += y;
        }
        warp_sums[lane] = s;
    }
    __syncthreads();
    int warp_off = (w > 0) ? warp_sums[w - 1] : 0;
    if (i < N_NODES) {
        int excl = base + warp_off + x - v;
        g_rowptr[i] = excl;
        g_cursor[i] = excl;
        float deg = (float)v + 1.0f;
        g_dinv[i]   = rsqrtf(deg);
        g_invdeg[i] = 1.0f / deg;
    }
}

__global__ void k_fill(const int* __restrict__ src, const int* __restrict__ dst) {
    int e = blockIdx.x * blockDim.x + threadIdx.x;
    if (e < N_EDGES) {
        int p = atomicAdd(&g_cursor[dst[e]], 1);
        g_col[p] = src[e];
    }
}

// ---------------- helpers ----------------
__device__ __forceinline__ uint32_t smem_u32(const void* p) {
    return (uint32_t)__cvta_generic_to_shared(p);
}
__device__ __forceinline__ uint32_t pack_bf2(float x, float y) {
    __nv_bfloat162 t = __floats2bfloat162_rn(x, y);
    return *reinterpret_cast<uint32_t*>(&t);
}

// ---------------- fused split-K reduce + f2 ----------------
#define RED_BLOCKS 3750
__global__ void k_redf2(const float* __restrict__ b1, const float* __restrict__ px,
                        const float* __restrict__ W2, const float* __restrict__ b2) {
    if (blockIdx.x < RED_BLOCKS) {
        int idx = blockIdx.x * 256 + threadIdx.x;   // N_NODES*32
        if (idx >= N_NODES * 32) return;
        int i = idx >> 5, v = idx & 31;
        float4 s = make_float4(0.f, 0.f, 0.f, 0.f);
#pragma unroll
        for (int p = 0; p < SPLITS; p++) {
            const float4* pp = (const float4*)(g_part + (size_t)p * N_NODES * 128);
            float4 a = pp[idx];
            s.x += a.x; s.y += a.y; s.z += a.z; s.w += a.w;
        }
        float4 bb = ((const float4*)b1)[v];
        float r0 = fmaxf(s.x + bb.x, 0.0f);
        float r1 = fmaxf(s.y + bb.y, 0.0f);
        float r2 = fmaxf(s.z + bb.z, 0.0f);
        float r3 = fmaxf(s.w + bb.w, 0.0f);
        uint32_t* dst = (uint32_t*)(g_X0b + (size_t)i * B149 + v * 2);
        dst[0] = pack_bf2(r0, r1);
        dst[1] = pack_bf2(r2, r3);
    } else {
        int warp = ((blockIdx.x - RED_BLOCKS) * 256 + threadIdx.x) >> 5;
        int lane = threadIdx.x & 31;
        if (warp >= N_NODES) return;
        float x = 0.0f;
        if (lane < AA) x = px[(size_t)warp * D_IN + lane];
        float acc = (lane < AA) ? b2[lane] : 0.0f;
#pragma unroll
        for (int k = 0; k < AA; k++) {
            float xk = __shfl_sync(0xffffffffu, x, k);
            if (lane < AA) acc += xk * W2[k * AA + lane];
        }
        if (lane < AA) {
            __nv_bfloat16* p = (__nv_bfloat16*)g_X0b;
            p[(size_t)warp * 152 + 128 + lane] = __float2bfloat16(fmaxf(acc, 0.0f));
        }
    }
}

// ================= dedicated f1 GEMM (tf32, BM=128/BK=32, proven) =================
#define F1_STAGES 3
#define ASTR_F1 36

__device__ __forceinline__ void f1_load_stage(
    float (*As)[ASTR_F1], float (*Bs)[136],
    const float* __restrict__ A, const float* __restrict__ Bp,
    int bm, int k0, int M, int warp, int lane, int tid)
{
#pragma unroll
    for (int i = 0; i < 16; i++) {
        int r = warp * 16 + i;
        int gm = bm + r;
        int bytes = (gm < M) ? 4 : 0;
        uint32_t dsta = smem_u32(&As[r][lane]);
        const float* ga = A + (size_t)gm * D_IN + k0 + lane;
        asm volatile("cp.async.ca.shared.global [%0], [%1], 4, %2;\n"
                     :: "r"(dsta), "l"(ga), "r"(bytes));
    }
#pragma unroll
    for (int ii = 0; ii < 4; ii++) {
        int idx = ii * 256 + tid;
        int bk = idx >> 5;
        int c4 = (idx & 31) << 2;
        uint32_t dstb = smem_u32(&Bs[bk][c4]);
        const float* gb = Bp + (size_t)(k0 + bk) * 128 + c4;
        asm volatile("cp.async.cg.shared.global [%0], [%1], 16, %2;\n"
                     :: "r"(dstb), "l"(gb), "r"(16));
    }
}

__global__ __launch_bounds__(256, 2)
void k_f1(const float* __restrict__ A, const float* __restrict__ Bp,
          float* __restrict__ Cpart, int M) {
    extern __shared__ float sm[];
    float (*As)[128][ASTR_F1] = reinterpret_cast<float(*)[128][ASTR_F1]>(sm);
    float (*Bs)[32][136] = reinterpret_cast<float(*)[32][136]>(sm + F1_STAGES * 128 * ASTR_F1);

    int tid = threadIdx.x;
    int lane = tid & 31, warp = tid >> 5;
    int wm = warp & 3, wn = warp >> 2;
    int q = lane & 3, g = lane >> 2;
    int bm = blockIdx.x * 128;
    int kbeg = blockIdx.z * KSPLIT;
    float* C = Cpart + (size_t)blockIdx.z * N_NODES * 128;

    float acc[2][8][4];
#pragma unroll
    for (int i = 0; i < 2; i++)
#pragma unroll
        for (int j = 0; j < 8; j++)
#pragma unroll
            for (int r = 0; r < 4; r++) acc[i][j][r] = 0.0f;

    const int T = KSPLIT / 32;

#pragma unroll
    for (int s = 0; s < F1_STAGES - 1; s++) {
        f1_load_stage(As[s], Bs[s], A, Bp, bm, kbeg + s * 32, M, warp, lane, tid);
        asm volatile("cp.async.commit_group;\n");
    }

    for (int t = 0; t < T; t++) {
        int nxt = t + F1_STAGES - 1;
        if (nxt < T) {
            int slot = nxt % F1_STAGES;
            f1_load_stage(As[slot], Bs[slot], A, Bp, bm, kbeg + nxt * 32, M, warp, lane, tid);
        }
        asm volatile("cp.async.commit_group;\n");
        asm volatile("cp.async.wait_group %0;\n" :: "n"(F1_STAGES - 1));
        __syncthreads();

        int cur = t % F1_STAGES;
#pragma unroll
        for (int sp = 0; sp < 4; sp++) {
            int s8 = sp * 8;
            uint32_t a[2][4];
#pragma unroll
            for (int i = 0; i < 2; i++) {
                int m = wm * 32 + i * 16 + g;
                a[i][0] = __float_as_uint(As[cur][m][s8 + q]);
                a[i][1] = __float_as_uint(As[cur][m + 8][s8 + q]);
                a[i][2] = __float_as_uint(As[cur][m][s8 + q + 4]);
                a[i][3] = __float_as_uint(As[cur][m + 8][s8 + q + 4]);
            }
            uint32_t b[8][2];
#pragma unroll
            for (int j = 0; j < 8; j++) {
                int n = wn * 64 + j * 8 + g;
                b[j][0] = __float_as_uint(Bs[cur][s8 + q][n]);
                b[j][1] = __float_as_uint(Bs[cur][s8 + q + 4][n]);
            }
#pragma unroll
            for (int i = 0; i < 2; i++)
#pragma unroll
                for (int j = 0; j < 8; j++) {
                    asm volatile(
                        "mma.sync.aligned.m16n8k8.row.col.f32.tf32.tf32.f32 "
                        "{%0,%1,%2,%3}, {%4,%5,%6,%7}, {%8,%9}, {%0,%1,%2,%3};\n"
                        : "+f"(acc[i][j][0]), "+f"(acc[i][j][1]),
                          "+f"(acc[i][j][2]), "+f"(acc[i][j][3])
                        : "r"(a[i][0]), "r"(a[i][1]), "r"(a[i][2]), "r"(a[i][3]),
                          "r"(b[j][0]), "r"(b[j][1]));
                }
        }
        __syncthreads();
    }

#pragma unroll
    for (int i = 0; i < 2; i++) {
        int row0 = bm + wm * 32 + i * 16 + g;
#pragma unroll
        for (int j = 0; j < 8; j++) {
            int col0 = wn * 64 + j * 8 + 2 * q;
            if (row0 < M) {
                C[(size_t)row0 * 128 + col0]     = acc[i][j][0];
                C[(size_t)row0 * 128 + col0 + 1] = acc[i][j][1];
            }
            if (row0 + 8 < M) {
                C[(size_t)(row0 + 8) * 128 + col0]     = acc[i][j][2];
                C[(size_t)(row0 + 8) * 128 + col0 + 1] = acc[i][j][3];
            }
        }
    }
}

// ================= bf16 conv GEMM: m16n8k16, BK=32, 3 stages =================
#define CSTAGE 3

__device__ __forceinline__ void load_stage_b16(
    uint32_t (*As)[20], uint32_t (*Bs)[20],
    const uint4* __restrict__ A4, int ldA4,
    const uint4* __restrict__ B4, int ldB4,
    int bm, int bn, int M, int k0, int tid)
{
    int kq = k0 >> 3;
#pragma unroll
    for (int p = 0; p < 2; p++) {
        int idx = p * 256 + tid;
        int r = idx >> 2, c = idx & 3;
        int gm = bm + r;
        int bytes = (gm < M) ? 16 : 0;
        uint32_t dsta = smem_u32(&As[r][c * 4]);
        const uint4* ga = A4 + (size_t)gm * ldA4 + kq + c;
        asm volatile("cp.async.cg.shared.global [%0], [%1], 16, %2;\n"
                     :: "r"(dsta), "l"(ga), "r"(bytes));
    }
#pragma unroll
    for (int p = 0; p < 2; p++) {
        int idx = p * 256 + tid;
        int r = idx >> 2, c = idx & 3;
        uint32_t dstb = smem_u32(&Bs[r][c * 4]);
        const uint4* gb = B4 + (size_t)(bn + r) * ldB4 + kq + c;
        asm volatile("cp.async.cg.shared.global [%0], [%1], 16, %2;\n"
                     :: "r"(dstb), "l"(gb), "r"(16));
    }
}

__global__ __launch_bounds__(256, 2)
void k_mmab(const uint4* __restrict__ A4, int ldA4,
            const uint4* __restrict__ B4, int ldB4,
            float* __restrict__ C, int ldc,
            __nv_bfloat162* __restrict__ Cb, int ldcb,
            const float* __restrict__ bias,
            const float* __restrict__ rowscale,
            int M, int Kp, int N) {
    extern __shared__ uint32_t smu[];
    uint32_t (*As)[128][20] = reinterpret_cast<uint32_t(*)[128][20]>(smu);
    uint32_t (*Bs)[128][20] = reinterpret_cast<uint32_t(*)[128][20]>(smu + CSTAGE * 128 * 20);

    int tid = threadIdx.x;
    int lane = tid & 31, warp = tid >> 5;
    int wm = warp & 3, wn = warp >> 2;
    int q = lane & 3, g = lane >> 2;
    int bm = blockIdx.x * 128;
    int bn = blockIdx.y * 128;

    float acc[2][8][4];
#pragma unroll
    for (int i = 0; i < 2; i++)
#pragma unroll
        for (int j = 0; j < 8; j++)
#pragma unroll
            for (int r = 0; r < 4; r++) acc[i][j][r] = 0.0f;

    const int T = Kp >> 5;

#pragma unroll
    for (int s = 0; s < CSTAGE - 1; s++) {
        if (s < T)
            load_stage_b16(As[s], Bs[s], A4, ldA4, B4, ldB4, bm, bn, M, s << 5, tid);
        asm volatile("cp.async.commit_group;\n");
    }

    for (int t = 0; t < T; t++) {
        int nxt = t + CSTAGE - 1;
        if (nxt < T) {
            int slot = nxt % CSTAGE;
            load_stage_b16(As[slot], Bs[slot], A4, ldA4, B4, ldB4, bm, bn, M, nxt << 5, tid);
        }
        asm volatile("cp.async.commit_group;\n");
        asm volatile("cp.async.wait_group %0;\n" :: "n"(CSTAGE - 1));
        __syncthreads();

        int cur = t % CSTAGE;
#pragma unroll
        for (int s = 0; s < 2; s++) {
            int h = s * 8;
            uint32_t a[2][4];
#pragma unroll
            for (int i = 0; i < 2; i++) {
                int m = wm * 32 + i * 16 + g;
                a[i][0] = As[cur][m][h + q];
                a[i][1] = As[cur][m + 8][h + q];
                a[i][2] = As[cur][m][h + q + 4];
                a[i][3] = As[cur][m + 8][h + q + 4];
            }
#pragma unroll
            for (int j = 0; j < 8; j++) {
                int n = wn * 64 + j * 8 + g;
                uint32_t b0 = Bs[cur][n][h + q];
                uint32_t b1 = Bs[cur][n][h + q + 4];
#pragma unroll
                for (int i = 0; i < 2; i++) {
                    asm volatile(
                        "mma.sync.aligned.m16n8k16.row.col.f32.bf16.bf16.f32 "
                        "{%0,%1,%2,%3}, {%4,%5,%6,%7}, {%8,%9}, {%0,%1,%2,%3};\n"
                        : "+f"(acc[i][j][0]), "+f"(acc[i][j][1]),
                          "+f"(acc[i][j][2]), "+f"(acc[i][j][3])
                        : "r"(a[i][0]), "r"(a[i][1]), "r"(a[i][2]), "r"(a[i][3]),
                          "r"(b0), "r"(b1));
                }
            }
        }
        __syncthreads();
    }

#pragma unroll
    for (int i = 0; i < 2; i++) {
        int row0 = bm + wm * 32 + i * 16 + g;
        float sc0 = 1.0f, sc1 = 1.0f;
        if (rowscale) {
            if (row0 < M)     sc0 = __ldg(&rowscale[row0]);
            if (row0 + 8 < M) sc1 = __ldg(&rowscale[row0 + 8]);
        }
#pragma unroll
        for (int j = 0; j < 8; j++) {
            int col0 = bn + wn * 64 + j * 8 + 2 * q;
            float bz0 = (col0 < N) ? __ldg(&bias[col0]) : 0.0f;
            float bz1 = (col0 + 1 < N) ? __ldg(&bias[col0 + 1]) : 0.0f;
            float v00 = sc0 * fmaxf(acc[i][j][0] + bz0, 0.0f);
            float v01 = sc0 * fmaxf(acc[i][j][1] + bz1, 0.0f);
            float v10 = sc1 * fmaxf(acc[i][j][2] + bz0, 0.0f);
            float v11 = sc1 * fmaxf(acc[i][j][3] + bz1, 0.0f);
            if (Cb) {
                bool c1ok = (col0 + 1 < N);
                if (row0 < M && col0 < N)
                    Cb[(size_t)row0 * ldcb + (col0 >> 1)] =
                        __floats2bfloat162_rn(v00, c1ok ? v01 : 0.0f);
                if (row0 + 8 < M && col0 < N)
                    Cb[(size_t)(row0 + 8) * ldcb + (col0 >> 1)] =
                        __floats2bfloat162_rn(v10, c1ok ? v11 : 0.0f);
            } else {
                if (row0 < M) {
                    if (col0 < N)     C[(size_t)row0 * ldc + col0]     = v00;
                    if (col0 + 1 < N) C[(size_t)row0 * ldc + col0 + 1] = v01;
                }
                if (row0 + 8 < M) {
                    if (col0 < N)     C[(size_t)(row0 + 8) * ldc + col0]     = v10;
                    if (col0 + 1 < N) C[(size_t)(row0 + 8) * ldc + col0 + 1] = v11;
                }
            }
        }
    }
}

// ---------------- bf16 gather aggregation -> bf16 AGG ----------------
__device__ __forceinline__ void accum8(float* acc, float d, uint4 v) {
    const __nv_bfloat162* p = (const __nv_bfloat162*)&v;
#pragma unroll
    for (int k = 0; k < 4; k++) {
        float2 f = __bfloat1622float2(p[k]);
        acc[2 * k]     += d * f.x;
        acc[2 * k + 1] += d * f.y;
    }
}
__device__ __forceinline__ void accum8_1(float* acc, uint4 v) {
    const __nv_bfloat162* p = (const __nv_bfloat162*)&v;
#pragma unroll
    for (int k = 0; k < 4; k++) {
        float2 f = __bfloat1622float2(p[k]);
        acc[2 * k]     += f.x;
        acc[2 * k + 1] += f.y;
    }
}

// conv1 input (unscaled X0b): OUT_i = dinv_i * sum dinv_j X_j + invdeg_i X_i
template<int NPB>
__global__ void k_aggb_old(const uint4* __restrict__ X, int ldx,
                           uint4* __restrict__ OUT, int ldo, int dataW) {
    int i = blockIdx.x * NPB + threadIdx.y;
    if (i >= N_NODES) return;
    int c = threadIdx.x;
    uint4* orow = OUT + (size_t)i * ldo;
    if (c >= dataW) {
        orow[c] = make_uint4(0u, 0u, 0u, 0u);
        return;
    }
    int beg = g_rowptr[i], end = g_rowptr[i + 1];
    float acc[8] = {0.f, 0.f, 0.f, 0.f, 0.f, 0.f, 0.f, 0.f};
    int e = beg;
    for (; e + 4 <= end; e += 4) {
        int j0 = g_col[e], j1 = g_col[e + 1], j2 = g_col[e + 2], j3 = g_col[e + 3];
        float d0 = g_dinv[j0], d1 = g_dinv[j1], d2 = g_dinv[j2], d3 = g_dinv[j3];
        uint4 v0 = X[(size_t)j0 * ldx + c];
        uint4 v1 = X[(size_t)j1 * ldx + c];
        uint4 v2 = X[(size_t)j2 * ldx + c];
        uint4 v3 = X[(size_t)j3 * ldx + c];
        accum8(acc, d0, v0); accum8(acc, d1, v1); accum8(acc, d2, v2); accum8(acc, d3, v3);
    }
    for (; e < end; e++) {
        int j = g_col[e];
        accum8(acc, g_dinv[j], X[(size_t)j * ldx + c]);
    }
    float di = g_dinv[i], vi = g_invdeg[i];
    float self[8] = {0.f, 0.f, 0.f, 0.f, 0.f, 0.f, 0.f, 0.f};
    accum8_1(self, X[(size_t)i * ldx + c]);
    uint4 o;
    o.x = pack_bf2(di * acc[0] + vi * self[0], di * acc[1] + vi * self[1]);
    o.y = pack_bf2(di * acc[2] + vi * self[2], di * acc[3] + vi * self[3]);
    o.z = pack_bf2(di * acc[4] + vi * self[4], di * acc[5] + vi * self[5]);
    o.w = pack_bf2(di * acc[6] + vi * self[6], di * acc[7] + vi * self[7]);
    orow[c] = o;
}

// scaled input Xs = dinv .* x : OUT_i = dinv_i * (Xs_i + sum Xs_j)
template<int NPB>
__global__ void k_aggb_s(const uint4* __restrict__ X, int ldx,
                         uint4* __restrict__ OUT, int ldo, int dataW) {
    int i = blockIdx.x * NPB + threadIdx.y;
    if (i >= N_NODES) return;
    int c = threadIdx.x;
    uint4* orow = OUT + (size_t)i * ldo;
    if (c >= dataW) {
        orow[c] = make_uint4(0u, 0u, 0u, 0u);
        return;
    }
    int beg = g_rowptr[i], end = g_rowptr[i + 1];
    float acc[8] = {0.f, 0.f, 0.f, 0.f, 0.f, 0.f, 0.f, 0.f};
    accum8_1(acc, X[(size_t)i * ldx + c]);
    int e = beg;
    for (; e + 4 <= end; e += 4) {
        int j0 = g_col[e], j1 = g_col[e + 1], j2 = g_col[e + 2], j3 = g_col[e + 3];
        uint4 v0 = X[(size_t)j0 * ldx + c];
        uint4 v1 = X[(size_t)j1 * ldx + c];
        uint4 v2 = X[(size_t)j2 * ldx + c];
        uint4 v3 = X[(size_t)j3 * ldx + c];
        accum8_1(acc, v0); accum8_1(acc, v1); accum8_1(acc, v2); accum8_1(acc, v3);
    }
    for (; e < end; e++) accum8_1(acc, X[(size_t)g_col[e] * ldx + c]);
    float di = g_dinv[i];
    uint4 o;
    o.x = pack_bf2(di * acc[0], di * acc[1]);
    o.y = pack_bf2(di * acc[2], di * acc[3]);
    o.z = pack_bf2(di * acc[4], di * acc[5]);
    o.w = pack_bf2(di * acc[6], di * acc[7]);
    orow[c] = o;
}

// ---------------- global mean pool (float4, X3 fp32) ----------------
__device__ __forceinline__ void add4(float4& s, float4 x) {
    s.x += x.x; s.y += x.y; s.z += x.z; s.w += x.w;
}
__device__ __forceinline__ int lower_bound_i(const int* a, int n, int v) {
    int lo = 0, hi = n;
    while (lo < hi) { int m = (lo + hi) >> 1; if (a[m] < v) lo = m + 1; else hi = m; }
    return lo;
}

__global__ void k_pool4(const int* __restrict__ batch) {
    int gq = blockIdx.x;
    __shared__ int s_beg, s_end;
    if (threadIdx.x == 0) {
        s_beg = lower_bound_i(batch, N_NODES, gq);
        s_end = lower_bound_i(batch, N_NODES, gq + 1);
    }
    __syncthreads();
    int c = threadIdx.x;
    if (c >= 150) return;
    const float4* X4 = (const float4*)g_X3;
    int beg = s_beg, end = s_end;
    float4 s = make_float4(0.f, 0.f, 0.f, 0.f);
    int n = beg;
    for (; n + 4 <= end; n += 4) {
        float4 x0 = X4[(size_t)n * 150 + c];
        float4 x1 = X4[(size_t)(n + 1) * 150 + c];
        float4 x2 = X4[(size_t)(n + 2) * 150 + c];
        float4 x3 = X4[(size_t)(n + 3) * 150 + c];
        add4(s, x0); add4(s, x1); add4(s, x2); add4(s, x3);
    }
    for (; n < end; n++) add4(s, X4[(size_t)n * 150 + c]);
    float inv = 1.0f / fmaxf((float)(end - beg), 1.0f);
    float4 r;
    r.x = s.x * inv; r.y = s.y * inv; r.z = s.z * inv; r.w = s.w * inv;
    ((float4*)g_pool)[(size_t)gq * 150 + c] = r;
}

// ---------------- FC head (R13 proven form) ----------------
__global__ void k_fc1(const float* __restrict__ Wg1, const float* __restrict__ bg1,
                      const float* __restrict__ gamma, const float* __restrict__ beta) {
    int gq = blockIdx.x;
    int o = threadIdx.x;
    __shared__ float xr[C3V];
    for (int c = threadIdx.x; c < C3V; c += blockDim.x) xr[c] = g_pool[gq * S596 + c];
    __syncthreads();
    float acc = bg1[o];
    for (int k = 0; k < C3V; k++) acc += xr[k] * Wg1[k * FC1V + o];
    float inv = 1.0f / sqrtf(1.0f + 1e-5f);
    acc = gamma[o] * (acc * inv) + beta[o];
    g_fc1[gq * FC1V + o] = fmaxf(acc, 0.0f);
}

__global__ void k_fc2(const float* __restrict__ Wg2, const float* __restrict__ bg2,
                      float* __restrict__ out) {
    int gq = blockIdx.x;
    int o = threadIdx.x;
    __shared__ float xr[FC1V];
    for (int c = threadIdx.x; c < FC1V; c += blockDim.x) xr[c] = g_fc1[gq * FC1V + c];
    __syncthreads();
    if (o < OUTV) {
        float acc = bg2[o];
        for (int k = 0; k < FC1V; k++) acc += xr[k] * Wg2[k * OUTV + o];
        out[gq * OUTV + o] = 1.0f / (1.0f + expf(-acc));
    }
}

// ---------------- launch ----------------
extern "C" void kernel_launch(void* const* d_in, const int* in_sizes, int n_in,
                              void* d_out, int out_size) {
    const float* prot_x = (const float*)d_in[0];
    const int*   src    = (const int*)d_in[1];
    const int*   dst    = (const int*)d_in[2];
    const int*   batch  = (const int*)d_in[3];
    const float* W1  = (const float*)d_in[4];
    const float* b1  = (const float*)d_in[5];
    const float* W2  = (const float*)d_in[6];
    const float* b2  = (const float*)d_in[7];
    const float* Wc1 = (const float*)d_in[8];
    const float* bc1 = (const float*)d_in[9];
    const float* Wc2 = (const float*)d_in[10];
    const float* bc2 = (const float*)d_in[11];
    const float* Wc3 = (const float*)d_in[12];
    const float* bc3 = (const float*)d_in[13];
    const float* Wg1 = (const float*)d_in[14];
    const float* bg1 = (const float*)d_in[15];
    const float* Wg2 = (const float*)d_in[16];
    const float* bg2 = (const float*)d_in[17];
    const float* gamma = (const float*)d_in[18];
    const float* beta  = (const float*)d_in[19];

    float *X3, *PART, *W1p, *dinv;
    __nv_bfloat162 *X0b, *X1b, *X2b;
    __nv_bfloat16 *AGGb, *W1b, *W2b2, *W3b;
    cudaGetSymbolAddress((void**)&X0b, g_X0b);
    cudaGetSymbolAddress((void**)&X1b, g_X1b);
    cudaGetSymbolAddress((void**)&X2b, g_X2b);
    cudaGetSymbolAddress((void**)&X3, g_X3);
    cudaGetSymbolAddress((void**)&AGGb, g_AGGb);
    cudaGetSymbolAddress((void**)&PART, g_part);
    cudaGetSymbolAddress((void**)&W1p, g_W1p);
    cudaGetSymbolAddress((void**)&W1b, g_Wc1pb);
    cudaGetSymbolAddress((void**)&W2b2, g_Wc2pb);
    cudaGetSymbolAddress((void**)&W3b, g_Wc3pb);
    cudaGetSymbolAddress((void**)&dinv, g_dinv);

    const int SMF1 = F1_STAGES * (128 * ASTR_F1 + 32 * 136) * 4;  // 107520
    const int SMC  = CSTAGE * 2 * 128 * 20 * 4;                   // 61440
    cudaFuncSetAttribute(k_f1,   cudaFuncAttributeMaxDynamicSharedMemorySize, SMF1);
    cudaFuncSetAttribute(k_mmab, cudaFuncAttributeMaxDynamicSharedMemorySize, SMC);

    const int PREP_TOTAL = W1P_SZ + PB1_SZ + PB2_SZ + PB3_SZ + N_EDGES;

    // 1-3: fused pack+count, parallel scan (2 phases)
    k_prep<<<(PREP_TOTAL + 255) / 256, 256>>>(W1, Wc1, Wc2, Wc3, dst);
    k_scan1<<<30, 1024>>>();
    k_scan2<<<30, 1024>>>();

    // 4: f1 GEMM (profiler window slot)
    k_f1<<<dim3(235, 1, SPLITS), 256, SMF1>>>(prot_x + AA, W1p, PART, N_NODES);

    // 5-6: CSR fill, fused reduce + f2 -> X0b
    k_fill<<<(N_EDGES + 255) / 256, 256>>>(src, dst);
    k_redf2<<<RED_BLOCKS * 2, 256>>>(b1, prot_x, W2, b2);

    // conv1: agg (unscaled X0b) -> bf16 AGGb(ld 20 u4); bf16 GEMM -> X1b (dinv-scaled)
    k_aggb_old<12><<<(N_NODES + 11) / 12, dim3(20, 12)>>>(
        (const uint4*)X0b, 19, (uint4*)AGGb, 20, 19);
    k_mmab<<<dim3(235, 2), 256, SMC>>>((const uint4*)AGGb, 20, (const uint4*)W1b, 20,
                                       nullptr, 0, X1b, B149,
                                       bc1, dinv, N_NODES, 160, C1V);
    // conv2
    k_aggb_s<12><<<(N_NODES + 11) / 12, dim3(20, 12)>>>(
        (const uint4*)X1b, 19, (uint4*)AGGb, 20, 19);
    k_mmab<<<dim3(235, 3), 256, SMC>>>((const uint4*)AGGb, 20, (const uint4*)W2b2, 20,
                                       nullptr, 0, X2b, B298,
                                       bc2, dinv, N_NODES, 160, C2V);
    // conv3 -> fp32 X3
    k_aggb_s<6><<<(N_NODES + 5) / 6, dim3(40, 6)>>>(
        (const uint4*)X2b, 38, (uint4*)AGGb, 40, 38);
    k_mmab<<<dim3(235, 5), 256, SMC>>>((const uint4*)AGGb, 40, (const uint4*)W3b, 40,
                                       X3, S596, nullptr, 0,
                                       bc3, nullptr, N_NODES, 320, C3V);

    // pool + head
    k_pool4<<<N_GRAPHS, 160>>>(batch);
    k_fc1<<<N_GRAPHS, FC1V>>>(Wg1, bg1, gamma, beta);
    k_fc2<<<N_GRAPHS, 512>>>(Wg2, bg2, (float*)d_out);
}

// round 16
// speedup vs baseline: 1.2016x; 1.0151x over previous
#include <cuda_runtime.h>
#include <cuda_bf16.h>
#include <math.h>
#include <stdint.h>

#define N_NODES 30000
#define N_EDGES 480000
#define N_GRAPHS 64
#define AA 21
#define HID 128
#define D_IN 6165
#define C1V 149
#define C2V 298
#define C3V 596
#define FC1V 1024
#define OUTV 486

#define S596 600

// bf162 strides (pairs)
#define B149 76     // 152 channels
#define B298 152    // 304 channels
#define B596 300    // 600 channels

#define SPLITS 6
#define KSPLIT 1024

// ---------------- scratch ----------------
__device__ __nv_bfloat162 g_X0b[(size_t)N_NODES * B149];   // [f1(128)|f2(21)], pads 0
__device__ __nv_bfloat162 g_X1b[(size_t)N_NODES * B149];   // dinv-scaled conv1 out
__device__ __nv_bfloat162 g_X2b[(size_t)N_NODES * B298];   // dinv-scaled conv2 out
__device__ __nv_bfloat162 g_X3b[(size_t)N_NODES * B596];   // conv3 out (bf16), pads 0
__device__ __nv_bfloat16 g_AGGb[(size_t)N_NODES * 320];    // bf16 agg buffer (<=320 ch)
__device__ float g_part[(size_t)SPLITS * N_NODES * 128];
__device__ float g_dinv[N_NODES];
__device__ float g_invdeg[N_NODES];
__device__ int   g_cnt[N_NODES];
__device__ int   g_bsum[32];
__device__ int   g_rowptr[N_NODES + 1];
__device__ int   g_cursor[N_NODES];
__device__ int   g_col[N_EDGES];
__device__ float g_pool[N_GRAPHS * S596];
__device__ float g_fc1[N_GRAPHS * FC1V];

// f1 weights: tf32-preconverted fp32
__device__ float g_W1p[(size_t)6144 * 128 + 64];
// conv weights: bf16, TRANSPOSED [n][k], fully padded (zero)
__device__ __nv_bfloat16 g_Wc1pb[(size_t)256 * 160];
__device__ __nv_bfloat16 g_Wc2pb[(size_t)384 * 160];
__device__ __nv_bfloat16 g_Wc3pb[(size_t)640 * 320];

#define W1P_SZ  (6144 * 128)
#define PB1_SZ  (256 * 160)
#define PB2_SZ  (384 * 160)
#define PB3_SZ  (640 * 320)

// ---------------- fused pack + edge count ----------------
__device__ __forceinline__ float to_tf32(float v) {
    uint32_t t;
    asm("cvt.rna.tf32.f32 %0, %1;" : "=r"(t) : "f"(v));
    return __uint_as_float(t);
}

__global__ void k_prep(const float* __restrict__ W1, const float* __restrict__ Wc1,
                       const float* __restrict__ Wc2, const float* __restrict__ Wc3,
                       const int* __restrict__ dst) {
    int i = blockIdx.x * blockDim.x + threadIdx.x;
    if (i < W1P_SZ) {
        g_W1p[i] = to_tf32(W1[i]);
        return;
    }
    i -= W1P_SZ;
    if (i < PB1_SZ) {
        int n = i / 160, k = i % 160;
        // X0 layout is [f1(128)|f2(21)]; original Wc1 rows are [f2(21)|f1(128)]
        int ksrc = (k < 128) ? (AA + k) : ((k < C1V) ? (k - 128) : -1);
        float v = (ksrc >= 0 && n < C1V) ? Wc1[(size_t)ksrc * C1V + n] : 0.0f;
        g_Wc1pb[i] = __float2bfloat16(v);
        return;
    }
    i -= PB1_SZ;
    if (i < PB2_SZ) {
        int n = i / 160, k = i % 160;
        float v = (n < C2V && k < C1V) ? Wc2[(size_t)k * C2V + n] : 0.0f;
        g_Wc2pb[i] = __float2bfloat16(v);
        return;
    }
    i -= PB2_SZ;
    if (i < PB3_SZ) {
        int n = i / 320, k = i % 320;
        float v = (n < C3V && k < C2V) ? Wc3[(size_t)k * C3V + n] : 0.0f;
        g_Wc3pb[i] = __float2bfloat16(v);
        return;
    }
    i -= PB3_SZ;
    if (i < N_EDGES) atomicAdd(&g_cnt[dst[i]], 1);
}

// ---------------- parallel scan: phase 1 = per-block totals ----------------
__global__ void k_scan1() {
    __shared__ int ws[32];
    int t = threadIdx.x, lane = t & 31, w = t >> 5;
    int i = blockIdx.x * 1024 + t;
    int v = (i < N_NODES) ? g_cnt[i] : 0;
    int x = v;
#pragma unroll
    for (int off = 16; off > 0; off >>= 1)
        x += __shfl_down_sync(0xffffffffu, x, off);
    if (lane == 0) ws[w] = x;
    __syncthreads();
    if (w == 0) {
        int s = ws[lane];
#pragma unroll
        for (int off = 16; off > 0; off >>= 1)
            s += __shfl_down_sync(0xffffffffu, s, off);
        if (lane == 0) g_bsum[blockIdx.x] = s;
    }
}

// ---------------- parallel scan: phase 2 = base + local scan + node prep ------
__global__ void k_scan2() {
    __shared__ int warp_sums[32];
    __shared__ int s_base;
    int b = blockIdx.x;
    int t = threadIdx.x, lane = t & 31, w = t >> 5;
    if (t == 0) s_base = 0;
    __syncthreads();
    if (w == 0) {
        int bs = (lane < 30) ? g_bsum[lane] : 0;
#pragma unroll
        for (int off = 1; off < 32; off <<= 1) {
            int y = __shfl_up_sync(0xffffffffu, bs, off);
            if (lane >= off) bs += y;
        }
        if (b > 0 && lane == b - 1) s_base = bs;           // exclusive base
        if (b == 29 && lane == 29) g_rowptr[N_NODES] = bs; // grand total
    }
    __syncthreads();
    int base = s_base;

    int i = b * 1024 + t;
    int v = (i < N_NODES) ? g_cnt[i] : 0;
    if (i < N_NODES) g_cnt[i] = 0;
    int x = v;
#pragma unroll
    for (int off = 1; off < 32; off <<= 1) {
        int y = __shfl_up_sync(0xffffffffu, x, off);
        if (lane >= off) x += y;
    }
    if (lane == 31) warp_sums[w] = x;
    __syncthreads();
    if (w == 0) {
        int s = warp_sums[lane];
#pragma unroll
        for (int off = 1; off < 32; off <<= 1) {
            int y = __shfl_up_sync(0xffffffffu, s, off);
            if (lane >= off) s += y;
        }
        warp_sums[lane] = s;
    }
    __syncthreads();
    int warp_off = (w > 0) ? warp_sums[w - 1] : 0;
    if (i < N_NODES) {
        int excl = base + warp_off + x - v;
        g_rowptr[i] = excl;
        g_cursor[i] = excl;
        float deg = (float)v + 1.0f;
        g_dinv[i]   = rsqrtf(deg);
        g_invdeg[i] = 1.0f / deg;
    }
}

__global__ void k_fill(const int* __restrict__ src, const int* __restrict__ dst) {
    int e = blockIdx.x * blockDim.x + threadIdx.x;
    if (e < N_EDGES) {
        int p = atomicAdd(&g_cursor[dst[e]], 1);
        g_col[p] = src[e];
    }
}

// ---------------- helpers ----------------
__device__ __forceinline__ uint32_t smem_u32(const void* p) {
    return (uint32_t)__cvta_generic_to_shared(p);
}
__device__ __forceinline__ uint32_t pack_bf2(float x, float y) {
    __nv_bfloat162 t = __floats2bfloat162_rn(x, y);
    return *reinterpret_cast<uint32_t*>(&t);
}

// ---------------- fused split-K reduce + f2 ----------------
#define RED_BLOCKS 3750
__global__ void k_redf2(const float* __restrict__ b1, const float* __restrict__ px,
                        const float* __restrict__ W2, const float* __restrict__ b2) {
    if (blockIdx.x < RED_BLOCKS) {
        int idx = blockIdx.x * 256 + threadIdx.x;   // N_NODES*32
        if (idx >= N_NODES * 32) return;
        int i = idx >> 5, v = idx & 31;
        float4 s = make_float4(0.f, 0.f, 0.f, 0.f);
#pragma unroll
        for (int p = 0; p < SPLITS; p++) {
            const float4* pp = (const float4*)(g_part + (size_t)p * N_NODES * 128);
            float4 a = pp[idx];
            s.x += a.x; s.y += a.y; s.z += a.z; s.w += a.w;
        }
        float4 bb = ((const float4*)b1)[v];
        float r0 = fmaxf(s.x + bb.x, 0.0f);
        float r1 = fmaxf(s.y + bb.y, 0.0f);
        float r2 = fmaxf(s.z + bb.z, 0.0f);
        float r3 = fmaxf(s.w + bb.w, 0.0f);
        uint32_t* dst = (uint32_t*)(g_X0b + (size_t)i * B149 + v * 2);
        dst[0] = pack_bf2(r0, r1);
        dst[1] = pack_bf2(r2, r3);
    } else {
        int warp = ((blockIdx.x - RED_BLOCKS) * 256 + threadIdx.x) >> 5;
        int lane = threadIdx.x & 31;
        if (warp >= N_NODES) return;
        float x = 0.0f;
        if (lane < AA) x = px[(size_t)warp * D_IN + lane];
        float acc = (lane < AA) ? b2[lane] : 0.0f;
#pragma unroll
        for (int k = 0; k < AA; k++) {
            float xk = __shfl_sync(0xffffffffu, x, k);
            if (lane < AA) acc += xk * W2[k * AA + lane];
        }
        if (lane < AA) {
            __nv_bfloat16* p = (__nv_bfloat16*)g_X0b;
            p[(size_t)warp * 152 + 128 + lane] = __float2bfloat16(fmaxf(acc, 0.0f));
        }
    }
}

// ================= dedicated f1 GEMM (tf32, BM=128/BK=32, proven) =================
#define F1_STAGES 3
#define ASTR_F1 36

__device__ __forceinline__ void f1_load_stage(
    float (*As)[ASTR_F1], float (*Bs)[136],
    const float* __restrict__ A, const float* __restrict__ Bp,
    int bm, int k0, int M, int warp, int lane, int tid)
{
#pragma unroll
    for (int i = 0; i < 16; i++) {
        int r = warp * 16 + i;
        int gm = bm + r;
        int bytes = (gm < M) ? 4 : 0;
        uint32_t dsta = smem_u32(&As[r][lane]);
        const float* ga = A + (size_t)gm * D_IN + k0 + lane;
        asm volatile("cp.async.ca.shared.global [%0], [%1], 4, %2;\n"
                     :: "r"(dsta), "l"(ga), "r"(bytes));
    }
#pragma unroll
    for (int ii = 0; ii < 4; ii++) {
        int idx = ii * 256 + tid;
        int bk = idx >> 5;
        int c4 = (idx & 31) << 2;
        uint32_t dstb = smem_u32(&Bs[bk][c4]);
        const float* gb = Bp + (size_t)(k0 + bk) * 128 + c4;
        asm volatile("cp.async.cg.shared.global [%0], [%1], 16, %2;\n"
                     :: "r"(dstb), "l"(gb), "r"(16));
    }
}

__global__ __launch_bounds__(256, 2)
void k_f1(const float* __restrict__ A, const float* __restrict__ Bp,
          float* __restrict__ Cpart, int M) {
    extern __shared__ float sm[];
    float (*As)[128][ASTR_F1] = reinterpret_cast<float(*)[128][ASTR_F1]>(sm);
    float (*Bs)[32][136] = reinterpret_cast<float(*)[32][136]>(sm + F1_STAGES * 128 * ASTR_F1);

    int tid = threadIdx.x;
    int lane = tid & 31, warp = tid >> 5;
    int wm = warp & 3, wn = warp >> 2;
    int q = lane & 3, g = lane >> 2;
    int bm = blockIdx.x * 128;
    int kbeg = blockIdx.z * KSPLIT;
    float* C = Cpart + (size_t)blockIdx.z * N_NODES * 128;

    float acc[2][8][4];
#pragma unroll
    for (int i = 0; i < 2; i++)
#pragma unroll
        for (int j = 0; j < 8; j++)
#pragma unroll
            for (int r = 0; r < 4; r++) acc[i][j][r] = 0.0f;

    const int T = KSPLIT / 32;

#pragma unroll
    for (int s = 0; s < F1_STAGES - 1; s++) {
        f1_load_stage(As[s], Bs[s], A, Bp, bm, kbeg + s * 32, M, warp, lane, tid);
        asm volatile("cp.async.commit_group;\n");
    }

    for (int t = 0; t < T; t++) {
        int nxt = t + F1_STAGES - 1;
        if (nxt < T) {
            int slot = nxt % F1_STAGES;
            f1_load_stage(As[slot], Bs[slot], A, Bp, bm, kbeg + nxt * 32, M, warp, lane, tid);
        }
        asm volatile("cp.async.commit_group;\n");
        asm volatile("cp.async.wait_group %0;\n" :: "n"(F1_STAGES - 1));
        __syncthreads();

        int cur = t % F1_STAGES;
#pragma unroll
        for (int sp = 0; sp < 4; sp++) {
            int s8 = sp * 8;
            uint32_t a[2][4];
#pragma unroll
            for (int i = 0; i < 2; i++) {
                int m = wm * 32 + i * 16 + g;
                a[i][0] = __float_as_uint(As[cur][m][s8 + q]);
                a[i][1] = __float_as_uint(As[cur][m + 8][s8 + q]);
                a[i][2] = __float_as_uint(As[cur][m][s8 + q + 4]);
                a[i][3] = __float_as_uint(As[cur][m + 8][s8 + q + 4]);
            }
            uint32_t b[8][2];
#pragma unroll
            for (int j = 0; j < 8; j++) {
                int n = wn * 64 + j * 8 + g;
                b[j][0] = __float_as_uint(Bs[cur][s8 + q][n]);
                b[j][1] = __float_as_uint(Bs[cur][s8 + q + 4][n]);
            }
#pragma unroll
            for (int i = 0; i < 2; i++)
#pragma unroll
                for (int j = 0; j < 8; j++) {
                    asm volatile(
                        "mma.sync.aligned.m16n8k8.row.col.f32.tf32.tf32.f32 "
                        "{%0,%1,%2,%3}, {%4,%5,%6,%7}, {%8,%9}, {%0,%1,%2,%3};\n"
                        : "+f"(acc[i][j][0]), "+f"(acc[i][j][1]),
                          "+f"(acc[i][j][2]), "+f"(acc[i][j][3])
                        : "r"(a[i][0]), "r"(a[i][1]), "r"(a[i][2]), "r"(a[i][3]),
                          "r"(b[j][0]), "r"(b[j][1]));
                }
        }
        __syncthreads();
    }

#pragma unroll
    for (int i = 0; i < 2; i++) {
        int row0 = bm + wm * 32 + i * 16 + g;
#pragma unroll
        for (int j = 0; j < 8; j++) {
            int col0 = wn * 64 + j * 8 + 2 * q;
            if (row0 < M) {
                C[(size_t)row0 * 128 + col0]     = acc[i][j][0];
                C[(size_t)row0 * 128 + col0 + 1] = acc[i][j][1];
            }
            if (row0 + 8 < M) {
                C[(size_t)(row0 + 8) * 128 + col0]     = acc[i][j][2];
                C[(size_t)(row0 + 8) * 128 + col0 + 1] = acc[i][j][3];
            }
        }
    }
}

// ================= bf16 conv GEMM: m16n8k16, BK=32, 4 stages =================
#define CSTAGE 4

__device__ __forceinline__ void load_stage_b16(
    uint32_t (*As)[20], uint32_t (*Bs)[20],
    const uint4* __restrict__ A4, int ldA4,
    const uint4* __restrict__ B4, int ldB4,
    int bm, int bn, int M, int k0, int tid)
{
    int kq = k0 >> 3;
#pragma unroll
    for (int p = 0; p < 2; p++) {
        int idx = p * 256 + tid;
        int r = idx >> 2, c = idx & 3;
        int gm = bm + r;
        int bytes = (gm < M) ? 16 : 0;
        uint32_t dsta = smem_u32(&As[r][c * 4]);
        const uint4* ga = A4 + (size_t)gm * ldA4 + kq + c;
        asm volatile("cp.async.cg.shared.global [%0], [%1], 16, %2;\n"
                     :: "r"(dsta), "l"(ga), "r"(bytes));
    }
#pragma unroll
    for (int p = 0; p < 2; p++) {
        int idx = p * 256 + tid;
        int r = idx >> 2, c = idx & 3;
        uint32_t dstb = smem_u32(&Bs[r][c * 4]);
        const uint4* gb = B4 + (size_t)(bn + r) * ldB4 + kq + c;
        asm volatile("cp.async.cg.shared.global [%0], [%1], 16, %2;\n"
                     :: "r"(dstb), "l"(gb), "r"(16));
    }
}

__global__ __launch_bounds__(256, 2)
void k_mmab(const uint4* __restrict__ A4, int ldA4,
            const uint4* __restrict__ B4, int ldB4,
            float* __restrict__ C, int ldc,
            __nv_bfloat162* __restrict__ Cb, int ldcb,
            const float* __restrict__ bias,
            const float* __restrict__ rowscale,
            int M, int Kp, int N) {
    extern __shared__ uint32_t smu[];
    uint32_t (*As)[128][20] = reinterpret_cast<uint32_t(*)[128][20]>(smu);
    uint32_t (*Bs)[128][20] = reinterpret_cast<uint32_t(*)[128][20]>(smu + CSTAGE * 128 * 20);

    int tid = threadIdx.x;
    int lane = tid & 31, warp = tid >> 5;
    int wm = warp & 3, wn = warp >> 2;
    int q = lane & 3, g = lane >> 2;
    int bm = blockIdx.x * 128;
    int bn = blockIdx.y * 128;

    float acc[2][8][4];
#pragma unroll
    for (int i = 0; i < 2; i++)
#pragma unroll
        for (int j = 0; j < 8; j++)
#pragma unroll
            for (int r = 0; r < 4; r++) acc[i][j][r] = 0.0f;

    const int T = Kp >> 5;

#pragma unroll
    for (int s = 0; s < CSTAGE - 1; s++) {
        if (s < T)
            load_stage_b16(As[s], Bs[s], A4, ldA4, B4, ldB4, bm, bn, M, s << 5, tid);
        asm volatile("cp.async.commit_group;\n");
    }

    for (int t = 0; t < T; t++) {
        int nxt = t + CSTAGE - 1;
        if (nxt < T) {
            int slot = nxt % CSTAGE;
            load_stage_b16(As[slot], Bs[slot], A4, ldA4, B4, ldB4, bm, bn, M, nxt << 5, tid);
        }
        asm volatile("cp.async.commit_group;\n");
        asm volatile("cp.async.wait_group %0;\n" :: "n"(CSTAGE - 1));
        __syncthreads();

        int cur = t % CSTAGE;
#pragma unroll
        for (int s = 0; s < 2; s++) {
            int h = s * 8;
            uint32_t a[2][4];
#pragma unroll
            for (int i = 0; i < 2; i++) {
                int m = wm * 32 + i * 16 + g;
                a[i][0] = As[cur][m][h + q];
                a[i][1] = As[cur][m + 8][h + q];
                a[i][2] = As[cur][m][h + q + 4];
                a[i][3] = As[cur][m + 8][h + q + 4];
            }
#pragma unroll
            for (int j = 0; j < 8; j++) {
                int n = wn * 64 + j * 8 + g;
                uint32_t b0 = Bs[cur][n][h + q];
                uint32_t b1 = Bs[cur][n][h + q + 4];
#pragma unroll
                for (int i = 0; i < 2; i++) {
                    asm volatile(
                        "mma.sync.aligned.m16n8k16.row.col.f32.bf16.bf16.f32 "
                        "{%0,%1,%2,%3}, {%4,%5,%6,%7}, {%8,%9}, {%0,%1,%2,%3};\n"
                        : "+f"(acc[i][j][0]), "+f"(acc[i][j][1]),
                          "+f"(acc[i][j][2]), "+f"(acc[i][j][3])
                        : "r"(a[i][0]), "r"(a[i][1]), "r"(a[i][2]), "r"(a[i][3]),
                          "r"(b0), "r"(b1));
                }
            }
        }
        __syncthreads();
    }

#pragma unroll
    for (int i = 0; i < 2; i++) {
        int row0 = bm + wm * 32 + i * 16 + g;
        float sc0 = 1.0f, sc1 = 1.0f;
        if (rowscale) {
            if (row0 < M)     sc0 = __ldg(&rowscale[row0]);
            if (row0 + 8 < M) sc1 = __ldg(&rowscale[row0 + 8]);
        }
#pragma unroll
        for (int j = 0; j < 8; j++) {
            int col0 = bn + wn * 64 + j * 8 + 2 * q;
            float bz0 = (col0 < N) ? __ldg(&bias[col0]) : 0.0f;
            float bz1 = (col0 + 1 < N) ? __ldg(&bias[col0 + 1]) : 0.0f;
            float v00 = sc0 * fmaxf(acc[i][j][0] + bz0, 0.0f);
            float v01 = sc0 * fmaxf(acc[i][j][1] + bz1, 0.0f);
            float v10 = sc1 * fmaxf(acc[i][j][2] + bz0, 0.0f);
            float v11 = sc1 * fmaxf(acc[i][j][3] + bz1, 0.0f);
            if (Cb) {
                bool c1ok = (col0 + 1 < N);
                if (row0 < M && col0 < N)
                    Cb[(size_t)row0 * ldcb + (col0 >> 1)] =
                        __floats2bfloat162_rn(v00, c1ok ? v01 : 0.0f);
                if (row0 + 8 < M && col0 < N)
                    Cb[(size_t)(row0 + 8) * ldcb + (col0 >> 1)] =
                        __floats2bfloat162_rn(v10, c1ok ? v11 : 0.0f);
            } else {
                if (row0 < M) {
                    if (col0 < N)     C[(size_t)row0 * ldc + col0]     = v00;
                    if (col0 + 1 < N) C[(size_t)row0 * ldc + col0 + 1] = v01;
                }
                if (row0 + 8 < M) {
                    if (col0 < N)     C[(size_t)(row0 + 8) * ldc + col0]     = v10;
                    if (col0 + 1 < N) C[(size_t)(row0 + 8) * ldc + col0 + 1] = v11;
                }
            }
        }
    }
}

// ---------------- bf16 gather aggregation -> bf16 AGG ----------------
__device__ __forceinline__ void accum8(float* acc, float d, uint4 v) {
    const __nv_bfloat162* p = (const __nv_bfloat162*)&v;
#pragma unroll
    for (int k = 0; k < 4; k++) {
        float2 f = __bfloat1622float2(p[k]);
        acc[2 * k]     += d * f.x;
        acc[2 * k + 1] += d * f.y;
    }
}
__device__ __forceinline__ void accum8_1(float* acc, uint4 v) {
    const __nv_bfloat162* p = (const __nv_bfloat162*)&v;
#pragma unroll
    for (int k = 0; k < 4; k++) {
        float2 f = __bfloat1622float2(p[k]);
        acc[2 * k]     += f.x;
        acc[2 * k + 1] += f.y;
    }
}

// conv1 input (unscaled X0b): OUT_i = dinv_i * sum dinv_j X_j + invdeg_i X_i
template<int NPB>
__global__ void k_aggb_old(const uint4* __restrict__ X, int ldx,
                           uint4* __restrict__ OUT, int ldo, int dataW) {
    int i = blockIdx.x * NPB + threadIdx.y;
    if (i >= N_NODES) return;
    int c = threadIdx.x;
    uint4* orow = OUT + (size_t)i * ldo;
    if (c >= dataW) {
        orow[c] = make_uint4(0u, 0u, 0u, 0u);
        return;
    }
    int beg = g_rowptr[i], end = g_rowptr[i + 1];
    float acc[8] = {0.f, 0.f, 0.f, 0.f, 0.f, 0.f, 0.f, 0.f};
    int e = beg;
    for (; e + 4 <= end; e += 4) {
        int j0 = g_col[e], j1 = g_col[e + 1], j2 = g_col[e + 2], j3 = g_col[e + 3];
        float d0 = g_dinv[j0], d1 = g_dinv[j1], d2 = g_dinv[j2], d3 = g_dinv[j3];
        uint4 v0 = X[(size_t)j0 * ldx + c];
        uint4 v1 = X[(size_t)j1 * ldx + c];
        uint4 v2 = X[(size_t)j2 * ldx + c];
        uint4 v3 = X[(size_t)j3 * ldx + c];
        accum8(acc, d0, v0); accum8(acc, d1, v1); accum8(acc, d2, v2); accum8(acc, d3, v3);
    }
    for (; e < end; e++) {
        int j = g_col[e];
        accum8(acc, g_dinv[j], X[(size_t)j * ldx + c]);
    }
    float di = g_dinv[i], vi = g_invdeg[i];
    float self[8] = {0.f, 0.f, 0.f, 0.f, 0.f, 0.f, 0.f, 0.f};
    accum8_1(self, X[(size_t)i * ldx + c]);
    uint4 o;
    o.x = pack_bf2(di * acc[0] + vi * self[0], di * acc[1] + vi * self[1]);
    o.y = pack_bf2(di * acc[2] + vi * self[2], di * acc[3] + vi * self[3]);
    o.z = pack_bf2(di * acc[4] + vi * self[4], di * acc[5] + vi * self[5]);
    o.w = pack_bf2(di * acc[6] + vi * self[6], di * acc[7] + vi * self[7]);
    orow[c] = o;
}

// scaled input Xs = dinv .* x : OUT_i = dinv_i * (Xs_i + sum Xs_j)
template<int NPB>
__global__ void k_aggb_s(const uint4* __restrict__ X, int ldx,
                         uint4* __restrict__ OUT, int ldo, int dataW) {
    int i = blockIdx.x * NPB + threadIdx.y;
    if (i >= N_NODES) return;
    int c = threadIdx.x;
    uint4* orow = OUT + (size_t)i * ldo;
    if (c >= dataW) {
        orow[c] = make_uint4(0u, 0u, 0u, 0u);
        return;
    }
    int beg = g_rowptr[i], end = g_rowptr[i + 1];
    float acc[8] = {0.f, 0.f, 0.f, 0.f, 0.f, 0.f, 0.f, 0.f};
    accum8_1(acc, X[(size_t)i * ldx + c]);
    int e = beg;
    for (; e + 4 <= end; e += 4) {
        int j0 = g_col[e], j1 = g_col[e + 1], j2 = g_col[e + 2], j3 = g_col[e + 3];
        uint4 v0 = X[(size_t)j0 * ldx + c];
        uint4 v1 = X[(size_t)j1 * ldx + c];
        uint4 v2 = X[(size_t)j2 * ldx + c];
        uint4 v3 = X[(size_t)j3 * ldx + c];
        accum8_1(acc, v0); accum8_1(acc, v1); accum8_1(acc, v2); accum8_1(acc, v3);
    }
    for (; e < end; e++) accum8_1(acc, X[(size_t)g_col[e] * ldx + c]);
    float di = g_dinv[i];
    uint4 o;
    o.x = pack_bf2(di * acc[0], di * acc[1]);
    o.y = pack_bf2(di * acc[2], di * acc[3]);
    o.z = pack_bf2(di * acc[4], di * acc[5]);
    o.w = pack_bf2(di * acc[6], di * acc[7]);
    orow[c] = o;
}

// ---------------- global mean pool (bf16 X3b -> fp32 pool) ----------------
__device__ __forceinline__ int lower_bound_i(const int* a, int n, int v) {
    int lo = 0, hi = n;
    while (lo < hi) { int m = (lo + hi) >> 1; if (a[m] < v) lo = m + 1; else hi = m; }
    return lo;
}

__global__ void k_pool4(const int* __restrict__ batch) {
    int gq = blockIdx.x;
    __shared__ int s_beg, s_end;
    if (threadIdx.x == 0) {
        s_beg = lower_bound_i(batch, N_NODES, gq);
        s_end = lower_bound_i(batch, N_NODES, gq + 1);
    }
    __syncthreads();
    int c = threadIdx.x;            // blockDim 80, active c < 75 (75 u4 = 600 ch)
    if (c >= 75) return;
    const uint4* X = (const uint4*)g_X3b;   // row = 75 uint4
    int beg = s_beg, end = s_end;
    float acc[8] = {0.f, 0.f, 0.f, 0.f, 0.f, 0.f, 0.f, 0.f};
    int n = beg;
    for (; n + 4 <= end; n += 4) {
        uint4 v0 = X[(size_t)n * 75 + c];
        uint4 v1 = X[(size_t)(n + 1) * 75 + c];
        uint4 v2 = X[(size_t)(n + 2) * 75 + c];
        uint4 v3 = X[(size_t)(n + 3) * 75 + c];
        accum8_1(acc, v0); accum8_1(acc, v1); accum8_1(acc, v2); accum8_1(acc, v3);
    }
    for (; n < end; n++) accum8_1(acc, X[(size_t)n * 75 + c]);
    float inv = 1.0f / fmaxf((float)(end - beg), 1.0f);
    float4 o0, o1;
    o0.x = acc[0] * inv; o0.y = acc[1] * inv; o0.z = acc[2] * inv; o0.w = acc[3] * inv;
    o1.x = acc[4] * inv; o1.y = acc[5] * inv; o1.z = acc[6] * inv; o1.w = acc[7] * inv;
    float4* prow = (float4*)(g_pool + (size_t)gq * S596);
    prow[c * 2]     = o0;
    prow[c * 2 + 1] = o1;
}

// ---------------- FC head (R13 proven form) ----------------
__global__ void k_fc1(const float* __restrict__ Wg1, const float* __restrict__ bg1,
                      const float* __restrict__ gamma, const float* __restrict__ beta) {
    int gq = blockIdx.x;
    int o = threadIdx.x;
    __shared__ float xr[C3V];
    for (int c = threadIdx.x; c < C3V; c += blockDim.x) xr[c] = g_pool[gq * S596 + c];
    __syncthreads();
    float acc = bg1[o];
    for (int k = 0; k < C3V; k++) acc += xr[k] * Wg1[k * FC1V + o];
    float inv = 1.0f / sqrtf(1.0f + 1e-5f);
    acc = gamma[o] * (acc * inv) + beta[o];
    g_fc1[gq * FC1V + o] = fmaxf(acc, 0.0f);
}

__global__ void k_fc2(const float* __restrict__ Wg2, const float* __restrict__ bg2,
                      float* __restrict__ out) {
    int gq = blockIdx.x;
    int o = threadIdx.x;
    __shared__ float xr[FC1V];
    for (int c = threadIdx.x; c < FC1V; c += blockDim.x) xr[c] = g_fc1[gq * FC1V + c];
    __syncthreads();
    if (o < OUTV) {
        float acc = bg2[o];
        for (int k = 0; k < FC1V; k++) acc += xr[k] * Wg2[k * OUTV + o];
        out[gq * OUTV + o] = 1.0f / (1.0f + expf(-acc));
    }
}

// ---------------- launch ----------------
extern "C" void kernel_launch(void* const* d_in, const int* in_sizes, int n_in,
                              void* d_out, int out_size) {
    const float* prot_x = (const float*)d_in[0];
    const int*   src    = (const int*)d_in[1];
    const int*   dst    = (const int*)d_in[2];
    const int*   batch  = (const int*)d_in[3];
    const float* W1  = (const float*)d_in[4];
    const float* b1  = (const float*)d_in[5];
    const float* W2  = (const float*)d_in[6];
    const float* b2  = (const float*)d_in[7];
    const float* Wc1 = (const float*)d_in[8];
    const float* bc1 = (const float*)d_in[9];
    const float* Wc2 = (const float*)d_in[10];
    const float* bc2 = (const float*)d_in[11];
    const float* Wc3 = (const float*)d_in[12];
    const float* bc3 = (const float*)d_in[13];
    const float* Wg1 = (const float*)d_in[14];
    const float* bg1 = (const float*)d_in[15];
    const float* Wg2 = (const float*)d_in[16];
    const float* bg2 = (const float*)d_in[17];
    const float* gamma = (const float*)d_in[18];
    const float* beta  = (const float*)d_in[19];

    float *PART, *W1p, *dinv;
    __nv_bfloat162 *X0b, *X1b, *X2b, *X3b;
    __nv_bfloat16 *AGGb, *W1b, *W2b2, *W3b;
    cudaGetSymbolAddress((void**)&X0b, g_X0b);
    cudaGetSymbolAddress((void**)&X1b, g_X1b);
    cudaGetSymbolAddress((void**)&X2b, g_X2b);
    cudaGetSymbolAddress((void**)&X3b, g_X3b);
    cudaGetSymbolAddress((void**)&AGGb, g_AGGb);
    cudaGetSymbolAddress((void**)&PART, g_part);
    cudaGetSymbolAddress((void**)&W1p, g_W1p);
    cudaGetSymbolAddress((void**)&W1b, g_Wc1pb);
    cudaGetSymbolAddress((void**)&W2b2, g_Wc2pb);
    cudaGetSymbolAddress((void**)&W3b, g_Wc3pb);
    cudaGetSymbolAddress((void**)&dinv, g_dinv);

    const int SMF1 = F1_STAGES * (128 * ASTR_F1 + 32 * 136) * 4;  // 107520
    const int SMC  = CSTAGE * 2 * 128 * 20 * 4;                   // 81920
    cudaFuncSetAttribute(k_f1,   cudaFuncAttributeMaxDynamicSharedMemorySize, SMF1);
    cudaFuncSetAttribute(k_mmab, cudaFuncAttributeMaxDynamicSharedMemorySize, SMC);

    const int PREP_TOTAL = W1P_SZ + PB1_SZ + PB2_SZ + PB3_SZ + N_EDGES;

    // 1-3: fused pack+count, parallel scan (2 phases)
    k_prep<<<(PREP_TOTAL + 255) / 256, 256>>>(W1, Wc1, Wc2, Wc3, dst);
    k_scan1<<<30, 1024>>>();
    k_scan2<<<30, 1024>>>();

    // 4: f1 GEMM (profiler window slot)
    k_f1<<<dim3(235, 1, SPLITS), 256, SMF1>>>(prot_x + AA, W1p, PART, N_NODES);

    // 5-6: CSR fill, fused reduce + f2 -> X0b
    k_fill<<<(N_EDGES + 255) / 256, 256>>>(src, dst);
    k_redf2<<<RED_BLOCKS * 2, 256>>>(b1, prot_x, W2, b2);

    // conv1: agg (unscaled X0b) -> bf16 AGGb(ld 20 u4); bf16 GEMM -> X1b (dinv-scaled)
    k_aggb_old<12><<<(N_NODES + 11) / 12, dim3(20, 12)>>>(
        (const uint4*)X0b, 19, (uint4*)AGGb, 20, 19);
    k_mmab<<<dim3(235, 2), 256, SMC>>>((const uint4*)AGGb, 20, (const uint4*)W1b, 20,
                                       nullptr, 0, X1b, B149,
                                       bc1, dinv, N_NODES, 160, C1V);
    // conv2
    k_aggb_s<12><<<(N_NODES + 11) / 12, dim3(20, 12)>>>(
        (const uint4*)X1b, 19, (uint4*)AGGb, 20, 19);
    k_mmab<<<dim3(235, 3), 256, SMC>>>((const uint4*)AGGb, 20, (const uint4*)W2b2, 20,
                                       nullptr, 0, X2b, B298,
                                       bc2, dinv, N_NODES, 160, C2V);
    // conv3 -> bf16 X3b
    k_aggb_s<6><<<(N_NODES + 5) / 6, dim3(40, 6)>>>(
        (const uint4*)X2b, 38, (uint4*)AGGb, 40, 38);
    k_mmab<<<dim3(235, 5), 256, SMC>>>((const uint4*)AGGb, 40, (const uint4*)W3b, 40,
                                       nullptr, 0, X3b, B596,
                                       bc3, nullptr, N_NODES, 320, C3V);

    // pool + head
    k_pool4<<<N_GRAPHS, 80>>>(batch);
    k_fc1<<<N_GRAPHS, FC1V>>>(Wg1, bg1, gamma, beta);
    k_fc2<<<N_GRAPHS, 512>>>(Wg2, bg2, (float*)d_out);
}

// round 17
// speedup vs baseline: 1.2149x; 1.0110x over previous
#include <cuda_runtime.h>
#include <cuda_bf16.h>
#include <math.h>
#include <stdint.h>

#define N_NODES 30000
#define N_EDGES 480000
#define N_GRAPHS 64
#define AA 21
#define HID 128
#define D_IN 6165
#define C1V 149
#define C2V 298
#define C3V 596
#define FC1V 1024
#define OUTV 486

#define S596 600

// bf162 strides (pairs)
#define B149 76     // 152 channels
#define B298 152    // 304 channels
#define B596 300    // 600 channels

#define SPLITS 6
#define KSPLIT 1024

// ---------------- scratch ----------------
__device__ __nv_bfloat162 g_X0b[(size_t)N_NODES * B149];   // [f1(128)|f2(21)], pads 0
__device__ __nv_bfloat162 g_X1b[(size_t)N_NODES * B149];   // dinv-scaled conv1 out
__device__ __nv_bfloat162 g_X2b[(size_t)N_NODES * B298];   // dinv-scaled conv2 out
__device__ __nv_bfloat162 g_X3b[(size_t)N_NODES * B596];   // conv3 out (bf16), pads 0
__device__ __nv_bfloat16 g_AGGb[(size_t)N_NODES * 320];    // bf16 agg buffer (<=320 ch)
__device__ __nv_bfloat162 g_partb[(size_t)SPLITS * N_NODES * 64];  // bf16 f1 partials
__device__ float g_dinv[N_NODES];
__device__ float g_invdeg[N_NODES];
__device__ int   g_cnt[N_NODES];
__device__ int   g_bsum[32];
__device__ int   g_rowptr[N_NODES + 1];
__device__ int   g_cursor[N_NODES];
__device__ int   g_col[N_EDGES];
__device__ float g_pool[N_GRAPHS * S596];
__device__ float g_fc1[N_GRAPHS * FC1V];

// f1 weights: tf32-preconverted fp32
__device__ float g_W1p[(size_t)6144 * 128 + 64];
// conv weights: bf16, TRANSPOSED [n][k], fully padded (zero)
__device__ __nv_bfloat16 g_Wc1pb[(size_t)256 * 160];
__device__ __nv_bfloat16 g_Wc2pb[(size_t)384 * 160];
__device__ __nv_bfloat16 g_Wc3pb[(size_t)640 * 320];

#define W1P_SZ  (6144 * 128)
#define PB1_SZ  (256 * 160)
#define PB2_SZ  (384 * 160)
#define PB3_SZ  (640 * 320)

// ---------------- fused pack + edge count ----------------
__device__ __forceinline__ float to_tf32(float v) {
    uint32_t t;
    asm("cvt.rna.tf32.f32 %0, %1;" : "=r"(t) : "f"(v));
    return __uint_as_float(t);
}

__global__ void k_prep(const float* __restrict__ W1, const float* __restrict__ Wc1,
                       const float* __restrict__ Wc2, const float* __restrict__ Wc3,
                       const int* __restrict__ dst) {
    int i = blockIdx.x * blockDim.x + threadIdx.x;
    if (i < W1P_SZ) {
        g_W1p[i] = to_tf32(W1[i]);
        return;
    }
    i -= W1P_SZ;
    if (i < PB1_SZ) {
        int n = i / 160, k = i % 160;
        // X0 layout is [f1(128)|f2(21)]; original Wc1 rows are [f2(21)|f1(128)]
        int ksrc = (k < 128) ? (AA + k) : ((k < C1V) ? (k - 128) : -1);
        float v = (ksrc >= 0 && n < C1V) ? Wc1[(size_t)ksrc * C1V + n] : 0.0f;
        g_Wc1pb[i] = __float2bfloat16(v);
        return;
    }
    i -= PB1_SZ;
    if (i < PB2_SZ) {
        int n = i / 160, k = i % 160;
        float v = (n < C2V && k < C1V) ? Wc2[(size_t)k * C2V + n] : 0.0f;
        g_Wc2pb[i] = __float2bfloat16(v);
        return;
    }
    i -= PB2_SZ;
    if (i < PB3_SZ) {
        int n = i / 320, k = i % 320;
        float v = (n < C3V && k < C2V) ? Wc3[(size_t)k * C3V + n] : 0.0f;
        g_Wc3pb[i] = __float2bfloat16(v);
        return;
    }
    i -= PB3_SZ;
    if (i < N_EDGES) atomicAdd(&g_cnt[dst[i]], 1);
}

// ---------------- parallel scan: phase 1 = per-block totals ----------------
__global__ void k_scan1() {
    __shared__ int ws[32];
    int t = threadIdx.x, lane = t & 31, w = t >> 5;
    int i = blockIdx.x * 1024 + t;
    int v = (i < N_NODES) ? g_cnt[i] : 0;
    int x = v;
#pragma unroll
    for (int off = 16; off > 0; off >>= 1)
        x += __shfl_down_sync(0xffffffffu, x, off);
    if (lane == 0) ws[w] = x;
    __syncthreads();
    if (w == 0) {
        int s = ws[lane];
#pragma unroll
        for (int off = 16; off > 0; off >>= 1)
            s += __shfl_down_sync(0xffffffffu, s, off);
        if (lane == 0) g_bsum[blockIdx.x] = s;
    }
}

// ---------------- parallel scan: phase 2 = base + local scan + node prep ------
__global__ void k_scan2() {
    __shared__ int warp_sums[32];
    __shared__ int s_base;
    int b = blockIdx.x;
    int t = threadIdx.x, lane = t & 31, w = t >> 5;
    if (t == 0) s_base = 0;
    __syncthreads();
    if (w == 0) {
        int bs = (lane < 30) ? g_bsum[lane] : 0;
#pragma unroll
        for (int off = 1; off < 32; off <<= 1) {
            int y = __shfl_up_sync(0xffffffffu, bs, off);
            if (lane >= off) bs += y;
        }
        if (b > 0 && lane == b - 1) s_base = bs;           // exclusive base
        if (b == 29 && lane == 29) g_rowptr[N_NODES] = bs; // grand total
    }
    __syncthreads();
    int base = s_base;

    int i = b * 1024 + t;
    int v = (i < N_NODES) ? g_cnt[i] : 0;
    if (i < N_NODES) g_cnt[i] = 0;
    int x = v;
#pragma unroll
    for (int off = 1; off < 32; off <<= 1) {
        int y = __shfl_up_sync(0xffffffffu, x, off);
        if (lane >= off) x += y;
    }
    if (lane == 31) warp_sums[w] = x;
    __syncthreads();
    if (w == 0) {
        int s = warp_sums[lane];
#pragma unroll
        for (int off = 1; off < 32; off <<= 1) {
            int y = __shfl_up_sync(0xffffffffu, s, off);
            if (lane >= off) s += y;
        }
        warp_sums[lane] = s;
    }
    __syncthreads();
    int warp_off = (w > 0) ? warp_sums[w - 1] : 0;
    if (i < N_NODES) {
        int excl = base + warp_off + x - v;
        g_rowptr[i] = excl;
        g_cursor[i] = excl;
        float deg = (float)v + 1.0f;
        g_dinv[i]   = rsqrtf(deg);
        g_invdeg[i] = 1.0f / deg;
    }
}

__global__ void k_fill(const int* __restrict__ src, const int* __restrict__ dst) {
    int e = blockIdx.x * blockDim.x + threadIdx.x;
    if (e < N_EDGES) {
        int p = atomicAdd(&g_cursor[dst[e]], 1);
        g_col[p] = src[e];
    }
}

// ---------------- helpers ----------------
__device__ __forceinline__ uint32_t smem_u32(const void* p) {
    return (uint32_t)__cvta_generic_to_shared(p);
}
__device__ __forceinline__ uint32_t pack_bf2(float x, float y) {
    __nv_bfloat162 t = __floats2bfloat162_rn(x, y);
    return *reinterpret_cast<uint32_t*>(&t);
}

// ---------------- fused split-K reduce (bf16 partials) + f2 ----------------
#define RED_BLOCKS 3750
__global__ void k_redf2(const float* __restrict__ b1, const float* __restrict__ px,
                        const float* __restrict__ W2, const float* __restrict__ b2) {
    if (blockIdx.x < RED_BLOCKS) {
        int idx = blockIdx.x * 256 + threadIdx.x;   // N_NODES*32 (4 ch each)
        if (idx >= N_NODES * 32) return;
        int i = idx >> 5, v = idx & 31;
        float s0 = 0.f, s1 = 0.f, s2 = 0.f, s3 = 0.f;
#pragma unroll
        for (int p = 0; p < SPLITS; p++) {
            const uint2* pp = (const uint2*)(g_partb + (size_t)p * N_NODES * 64);
            uint2 a = pp[idx];
            float2 f0 = __bfloat1622float2(*reinterpret_cast<__nv_bfloat162*>(&a.x));
            float2 f1 = __bfloat1622float2(*reinterpret_cast<__nv_bfloat162*>(&a.y));
            s0 += f0.x; s1 += f0.y; s2 += f1.x; s3 += f1.y;
        }
        float4 bb = ((const float4*)b1)[v];
        float r0 = fmaxf(s0 + bb.x, 0.0f);
        float r1 = fmaxf(s1 + bb.y, 0.0f);
        float r2 = fmaxf(s2 + bb.z, 0.0f);
        float r3 = fmaxf(s3 + bb.w, 0.0f);
        uint32_t* dst = (uint32_t*)(g_X0b + (size_t)i * B149 + v * 2);
        dst[0] = pack_bf2(r0, r1);
        dst[1] = pack_bf2(r2, r3);
    } else {
        int warp = ((blockIdx.x - RED_BLOCKS) * 256 + threadIdx.x) >> 5;
        int lane = threadIdx.x & 31;
        if (warp >= N_NODES) return;
        float x = 0.0f;
        if (lane < AA) x = px[(size_t)warp * D_IN + lane];
        float acc = (lane < AA) ? b2[lane] : 0.0f;
#pragma unroll
        for (int k = 0; k < AA; k++) {
            float xk = __shfl_sync(0xffffffffu, x, k);
            if (lane < AA) acc += xk * W2[k * AA + lane];
        }
        if (lane < AA) {
            __nv_bfloat16* p = (__nv_bfloat16*)g_X0b;
            p[(size_t)warp * 152 + 128 + lane] = __float2bfloat16(fmaxf(acc, 0.0f));
        }
    }
}

// ================= dedicated f1 GEMM (tf32, BM=128/BK=32, bf16 partial out) ======
#define F1_STAGES 3
#define ASTR_F1 36

__device__ __forceinline__ void f1_load_stage(
    float (*As)[ASTR_F1], float (*Bs)[136],
    const float* __restrict__ A, const float* __restrict__ Bp,
    int bm, int k0, int M, int warp, int lane, int tid)
{
#pragma unroll
    for (int i = 0; i < 16; i++) {
        int r = warp * 16 + i;
        int gm = bm + r;
        int bytes = (gm < M) ? 4 : 0;
        uint32_t dsta = smem_u32(&As[r][lane]);
        const float* ga = A + (size_t)gm * D_IN + k0 + lane;
        asm volatile("cp.async.ca.shared.global [%0], [%1], 4, %2;\n"
                     :: "r"(dsta), "l"(ga), "r"(bytes));
    }
#pragma unroll
    for (int ii = 0; ii < 4; ii++) {
        int idx = ii * 256 + tid;
        int bk = idx >> 5;
        int c4 = (idx & 31) << 2;
        uint32_t dstb = smem_u32(&Bs[bk][c4]);
        const float* gb = Bp + (size_t)(k0 + bk) * 128 + c4;
        asm volatile("cp.async.cg.shared.global [%0], [%1], 16, %2;\n"
                     :: "r"(dstb), "l"(gb), "r"(16));
    }
}

__global__ __launch_bounds__(256, 2)
void k_f1(const float* __restrict__ A, const float* __restrict__ Bp,
          __nv_bfloat162* __restrict__ Cpart, int M) {
    extern __shared__ float sm[];
    float (*As)[128][ASTR_F1] = reinterpret_cast<float(*)[128][ASTR_F1]>(sm);
    float (*Bs)[32][136] = reinterpret_cast<float(*)[32][136]>(sm + F1_STAGES * 128 * ASTR_F1);

    int tid = threadIdx.x;
    int lane = tid & 31, warp = tid >> 5;
    int wm = warp & 3, wn = warp >> 2;
    int q = lane & 3, g = lane >> 2;
    int bm = blockIdx.x * 128;
    int kbeg = blockIdx.z * KSPLIT;
    __nv_bfloat162* C = Cpart + (size_t)blockIdx.z * N_NODES * 64;

    float acc[2][8][4];
#pragma unroll
    for (int i = 0; i < 2; i++)
#pragma unroll
        for (int j = 0; j < 8; j++)
#pragma unroll
            for (int r = 0; r < 4; r++) acc[i][j][r] = 0.0f;

    const int T = KSPLIT / 32;

#pragma unroll
    for (int s = 0; s < F1_STAGES - 1; s++) {
        f1_load_stage(As[s], Bs[s], A, Bp, bm, kbeg + s * 32, M, warp, lane, tid);
        asm volatile("cp.async.commit_group;\n");
    }

    for (int t = 0; t < T; t++) {
        int nxt = t + F1_STAGES - 1;
        if (nxt < T) {
            int slot = nxt % F1_STAGES;
            f1_load_stage(As[slot], Bs[slot], A, Bp, bm, kbeg + nxt * 32, M, warp, lane, tid);
        }
        asm volatile("cp.async.commit_group;\n");
        asm volatile("cp.async.wait_group %0;\n" :: "n"(F1_STAGES - 1));
        __syncthreads();

        int cur = t % F1_STAGES;
#pragma unroll
        for (int sp = 0; sp < 4; sp++) {
            int s8 = sp * 8;
            uint32_t a[2][4];
#pragma unroll
            for (int i = 0; i < 2; i++) {
                int m = wm * 32 + i * 16 + g;
                a[i][0] = __float_as_uint(As[cur][m][s8 + q]);
                a[i][1] = __float_as_uint(As[cur][m + 8][s8 + q]);
                a[i][2] = __float_as_uint(As[cur][m][s8 + q + 4]);
                a[i][3] = __float_as_uint(As[cur][m + 8][s8 + q + 4]);
            }
            uint32_t b[8][2];
#pragma unroll
            for (int j = 0; j < 8; j++) {
                int n = wn * 64 + j * 8 + g;
                b[j][0] = __float_as_uint(Bs[cur][s8 + q][n]);
                b[j][1] = __float_as_uint(Bs[cur][s8 + q + 4][n]);
            }
#pragma unroll
            for (int i = 0; i < 2; i++)
#pragma unroll
                for (int j = 0; j < 8; j++) {
                    asm volatile(
                        "mma.sync.aligned.m16n8k8.row.col.f32.tf32.tf32.f32 "
                        "{%0,%1,%2,%3}, {%4,%5,%6,%7}, {%8,%9}, {%0,%1,%2,%3};\n"
                        : "+f"(acc[i][j][0]), "+f"(acc[i][j][1]),
                          "+f"(acc[i][j][2]), "+f"(acc[i][j][3])
                        : "r"(a[i][0]), "r"(a[i][1]), "r"(a[i][2]), "r"(a[i][3]),
                          "r"(b[j][0]), "r"(b[j][1]));
                }
        }
        __syncthreads();
    }

    // bf16 partial store (N==128 -> 64 bf162 per row), coalesced (pairs)
#pragma unroll
    for (int i = 0; i < 2; i++) {
        int row0 = bm + wm * 32 + i * 16 + g;
#pragma unroll
        for (int j = 0; j < 8; j++) {
            int col0 = wn * 64 + j * 8 + 2 * q;   // even
            if (row0 < M) {
                uint32_t pk = pack_bf2(acc[i][j][0], acc[i][j][1]);
                *((uint32_t*)(C + (size_t)row0 * 64 + (col0 >> 1))) = pk;
            }
            if (row0 + 8 < M) {
                uint32_t pk = pack_bf2(acc[i][j][2], acc[i][j][3]);
                *((uint32_t*)(C + (size_t)(row0 + 8) * 64 + (col0 >> 1))) = pk;
            }
        }
    }
}

// ================= bf16 conv GEMM: m16n8k16, BK=32, 4 stages =================
#define CSTAGE 4

__device__ __forceinline__ void load_stage_b16(
    uint32_t (*As)[20], uint32_t (*Bs)[20],
    const uint4* __restrict__ A4, int ldA4,
    const uint4* __restrict__ B4, int ldB4,
    int bm, int bn, int M, int k0, int tid)
{
    int kq = k0 >> 3;
#pragma unroll
    for (int p = 0; p < 2; p++) {
        int idx = p * 256 + tid;
        int r = idx >> 2, c = idx & 3;
        int gm = bm + r;
        int bytes = (gm < M) ? 16 : 0;
        uint32_t dsta = smem_u32(&As[r][c * 4]);
        const uint4* ga = A4 + (size_t)gm * ldA4 + kq + c;
        asm volatile("cp.async.cg.shared.global [%0], [%1], 16, %2;\n"
                     :: "r"(dsta), "l"(ga), "r"(bytes));
    }
#pragma unroll
    for (int p = 0; p < 2; p++) {
        int idx = p * 256 + tid;
        int r = idx >> 2, c = idx & 3;
        uint32_t dstb = smem_u32(&Bs[r][c * 4]);
        const uint4* gb = B4 + (size_t)(bn + r) * ldB4 + kq + c;
        asm volatile("cp.async.cg.shared.global [%0], [%1], 16, %2;\n"
                     :: "r"(dstb), "l"(gb), "r"(16));
    }
}

__global__ __launch_bounds__(256, 2)
void k_mmab(const uint4* __restrict__ A4, int ldA4,
            const uint4* __restrict__ B4, int ldB4,
            float* __restrict__ C, int ldc,
            __nv_bfloat162* __restrict__ Cb, int ldcb,
            const float* __restrict__ bias,
            const float* __restrict__ rowscale,
            int M, int Kp, int N) {
    extern __shared__ uint32_t smu[];
    uint32_t (*As)[128][20] = reinterpret_cast<uint32_t(*)[128][20]>(smu);
    uint32_t (*Bs)[128][20] = reinterpret_cast<uint32_t(*)[128][20]>(smu + CSTAGE * 128 * 20);

    int tid = threadIdx.x;
    int lane = tid & 31, warp = tid >> 5;
    int wm = warp & 3, wn = warp >> 2;
    int q = lane & 3, g = lane >> 2;
    int bm = blockIdx.x * 128;
    int bn = blockIdx.y * 128;

    float acc[2][8][4];
#pragma unroll
    for (int i = 0; i < 2; i++)
#pragma unroll
        for (int j = 0; j < 8; j++)
#pragma unroll
            for (int r = 0; r < 4; r++) acc[i][j][r] = 0.0f;

    const int T = Kp >> 5;

#pragma unroll
    for (int s = 0; s < CSTAGE - 1; s++) {
        if (s < T)
            load_stage_b16(As[s], Bs[s], A4, ldA4, B4, ldB4, bm, bn, M, s << 5, tid);
        asm volatile("cp.async.commit_group;\n");
    }

    for (int t = 0; t < T; t++) {
        int nxt = t + CSTAGE - 1;
        if (nxt < T) {
            int slot = nxt % CSTAGE;
            load_stage_b16(As[slot], Bs[slot], A4, ldA4, B4, ldB4, bm, bn, M, nxt << 5, tid);
        }
        asm volatile("cp.async.commit_group;\n");
        asm volatile("cp.async.wait_group %0;\n" :: "n"(CSTAGE - 1));
        __syncthreads();

        int cur = t % CSTAGE;
#pragma unroll
        for (int s = 0; s < 2; s++) {
            int h = s * 8;
            uint32_t a[2][4];
#pragma unroll
            for (int i = 0; i < 2; i++) {
                int m = wm * 32 + i * 16 + g;
                a[i][0] = As[cur][m][h + q];
                a[i][1] = As[cur][m + 8][h + q];
                a[i][2] = As[cur][m][h + q + 4];
                a[i][3] = As[cur][m + 8][h + q + 4];
            }
#pragma unroll
            for (int j = 0; j < 8; j++) {
                int n = wn * 64 + j * 8 + g;
                uint32_t b0 = Bs[cur][n][h + q];
                uint32_t b1 = Bs[cur][n][h + q + 4];
#pragma unroll
                for (int i = 0; i < 2; i++) {
                    asm volatile(
                        "mma.sync.aligned.m16n8k16.row.col.f32.bf16.bf16.f32 "
                        "{%0,%1,%2,%3}, {%4,%5,%6,%7}, {%8,%9}, {%0,%1,%2,%3};\n"
                        : "+f"(acc[i][j][0]), "+f"(acc[i][j][1]),
                          "+f"(acc[i][j][2]), "+f"(acc[i][j][3])
                        : "r"(a[i][0]), "r"(a[i][1]), "r"(a[i][2]), "r"(a[i][3]),
                          "r"(b0), "r"(b1));
                }
            }
        }
        __syncthreads();
    }

#pragma unroll
    for (int i = 0; i < 2; i++) {
        int row0 = bm + wm * 32 + i * 16 + g;
        float sc0 = 1.0f, sc1 = 1.0f;
        if (rowscale) {
            if (row0 < M)     sc0 = __ldg(&rowscale[row0]);
            if (row0 + 8 < M) sc1 = __ldg(&rowscale[row0 + 8]);
        }
#pragma unroll
        for (int j = 0; j < 8; j++) {
            int col0 = bn + wn * 64 + j * 8 + 2 * q;
            float bz0 = (col0 < N) ? __ldg(&bias[col0]) : 0.0f;
            float bz1 = (col0 + 1 < N) ? __ldg(&bias[col0 + 1]) : 0.0f;
            float v00 = sc0 * fmaxf(acc[i][j][0] + bz0, 0.0f);
            float v01 = sc0 * fmaxf(acc[i][j][1] + bz1, 0.0f);
            float v10 = sc1 * fmaxf(acc[i][j][2] + bz0, 0.0f);
            float v11 = sc1 * fmaxf(acc[i][j][3] + bz1, 0.0f);
            if (Cb) {
                bool c1ok = (col0 + 1 < N);
                if (row0 < M && col0 < N)
                    Cb[(size_t)row0 * ldcb + (col0 >> 1)] =
                        __floats2bfloat162_rn(v00, c1ok ? v01 : 0.0f);
                if (row0 + 8 < M && col0 < N)
                    Cb[(size_t)(row0 + 8) * ldcb + (col0 >> 1)] =
                        __floats2bfloat162_rn(v10, c1ok ? v11 : 0.0f);
            } else {
                if (row0 < M) {
                    if (col0 < N)     C[(size_t)row0 * ldc + col0]     = v00;
                    if (col0 + 1 < N) C[(size_t)row0 * ldc + col0 + 1] = v01;
                }
                if (row0 + 8 < M) {
                    if (col0 < N)     C[(size_t)(row0 + 8) * ldc + col0]     = v10;
                    if (col0 + 1 < N) C[(size_t)(row0 + 8) * ldc + col0 + 1] = v11;
                }
            }
        }
    }
}

// ---------------- bf16 gather aggregation -> bf16 AGG ----------------
__device__ __forceinline__ void accum8(float* acc, float d, uint4 v) {
    const __nv_bfloat162* p = (const __nv_bfloat162*)&v;
#pragma unroll
    for (int k = 0; k < 4; k++) {
        float2 f = __bfloat1622float2(p[k]);
        acc[2 * k]     += d * f.x;
        acc[2 * k + 1] += d * f.y;
    }
}
__device__ __forceinline__ void accum8_1(float* acc, uint4 v) {
    const __nv_bfloat162* p = (const __nv_bfloat162*)&v;
#pragma unroll
    for (int k = 0; k < 4; k++) {
        float2 f = __bfloat1622float2(p[k]);
        acc[2 * k]     += f.x;
        acc[2 * k + 1] += f.y;
    }
}

// conv1 input (unscaled X0b): OUT_i = dinv_i * sum dinv_j X_j + invdeg_i X_i
template<int NPB>
__global__ void k_aggb_old(const uint4* __restrict__ X, int ldx,
                           uint4* __restrict__ OUT, int ldo, int dataW) {
    int i = blockIdx.x * NPB + threadIdx.y;
    if (i >= N_NODES) return;
    int c = threadIdx.x;
    uint4* orow = OUT + (size_t)i * ldo;
    if (c >= dataW) {
        orow[c] = make_uint4(0u, 0u, 0u, 0u);
        return;
    }
    int beg = g_rowptr[i], end = g_rowptr[i + 1];
    float acc[8] = {0.f, 0.f, 0.f, 0.f, 0.f, 0.f, 0.f, 0.f};
    int e = beg;
    for (; e + 4 <= end; e += 4) {
        int j0 = g_col[e], j1 = g_col[e + 1], j2 = g_col[e + 2], j3 = g_col[e + 3];
        float d0 = g_dinv[j0], d1 = g_dinv[j1], d2 = g_dinv[j2], d3 = g_dinv[j3];
        uint4 v0 = X[(size_t)j0 * ldx + c];
        uint4 v1 = X[(size_t)j1 * ldx + c];
        uint4 v2 = X[(size_t)j2 * ldx + c];
        uint4 v3 = X[(size_t)j3 * ldx + c];
        accum8(acc, d0, v0); accum8(acc, d1, v1); accum8(acc, d2, v2); accum8(acc, d3, v3);
    }
    for (; e < end; e++) {
        int j = g_col[e];
        accum8(acc, g_dinv[j], X[(size_t)j * ldx + c]);
    }
    float di = g_dinv[i], vi = g_invdeg[i];
    float self[8] = {0.f, 0.f, 0.f, 0.f, 0.f, 0.f, 0.f, 0.f};
    accum8_1(self, X[(size_t)i * ldx + c]);
    uint4 o;
    o.x = pack_bf2(di * acc[0] + vi * self[0], di * acc[1] + vi * self[1]);
    o.y = pack_bf2(di * acc[2] + vi * self[2], di * acc[3] + vi * self[3]);
    o.z = pack_bf2(di * acc[4] + vi * self[4], di * acc[5] + vi * self[5]);
    o.w = pack_bf2(di * acc[6] + vi * self[6], di * acc[7] + vi * self[7]);
    orow[c] = o;
}

// scaled input Xs = dinv .* x : OUT_i = dinv_i * (Xs_i + sum Xs_j)
template<int NPB>
__global__ void k_aggb_s(const uint4* __restrict__ X, int ldx,
                         uint4* __restrict__ OUT, int ldo, int dataW) {
    int i = blockIdx.x * NPB + threadIdx.y;
    if (i >= N_NODES) return;
    int c = threadIdx.x;
    uint4* orow = OUT + (size_t)i * ldo;
    if (c >= dataW) {
        orow[c] = make_uint4(0u, 0u, 0u, 0u);
        return;
    }
    int beg = g_rowptr[i], end = g_rowptr[i + 1];
    float acc[8] = {0.f, 0.f, 0.f, 0.f, 0.f, 0.f, 0.f, 0.f};
    accum8_1(acc, X[(size_t)i * ldx + c]);
    int e = beg;
    for (; e + 4 <= end; e += 4) {
        int j0 = g_col[e], j1 = g_col[e + 1], j2 = g_col[e + 2], j3 = g_col[e + 3];
        uint4 v0 = X[(size_t)j0 * ldx + c];
        uint4 v1 = X[(size_t)j1 * ldx + c];
        uint4 v2 = X[(size_t)j2 * ldx + c];
        uint4 v3 = X[(size_t)j3 * ldx + c];
        accum8_1(acc, v0); accum8_1(acc, v1); accum8_1(acc, v2); accum8_1(acc, v3);
    }
    for (; e < end; e++) accum8_1(acc, X[(size_t)g_col[e] * ldx + c]);
    float di = g_dinv[i];
    uint4 o;
    o.x = pack_bf2(di * acc[0], di * acc[1]);
    o.y = pack_bf2(di * acc[2], di * acc[3]);
    o.z = pack_bf2(di * acc[4], di * acc[5]);
    o.w = pack_bf2(di * acc[6], di * acc[7]);
    orow[c] = o;
}

// ---------------- global mean pool (bf16 X3b -> fp32 pool) ----------------
__device__ __forceinline__ int lower_bound_i(const int* a, int n, int v) {
    int lo = 0, hi = n;
    while (lo < hi) { int m = (lo + hi) >> 1; if (a[m] < v) lo = m + 1; else hi = m; }
    return lo;
}

__global__ void k_pool4(const int* __restrict__ batch) {
    int gq = blockIdx.x;
    __shared__ int s_beg, s_end;
    if (threadIdx.x == 0) {
        s_beg = lower_bound_i(batch, N_NODES, gq);
        s_end = lower_bound_i(batch, N_NODES, gq + 1);
    }
    __syncthreads();
    int c = threadIdx.x;            // blockDim 80, active c < 75 (75 u4 = 600 ch)
    if (c >= 75) return;
    const uint4* X = (const uint4*)g_X3b;   // row = 75 uint4
    int beg = s_beg, end = s_end;
    float acc[8] = {0.f, 0.f, 0.f, 0.f, 0.f, 0.f, 0.f, 0.f};
    int n = beg;
    for (; n + 4 <= end; n += 4) {
        uint4 v0 = X[(size_t)n * 75 + c];
        uint4 v1 = X[(size_t)(n + 1) * 75 + c];
        uint4 v2 = X[(size_t)(n + 2) * 75 + c];
        uint4 v3 = X[(size_t)(n + 3) * 75 + c];
        accum8_1(acc, v0); accum8_1(acc, v1); accum8_1(acc, v2); accum8_1(acc, v3);
    }
    for (; n < end; n++) accum8_1(acc, X[(size_t)n * 75 + c]);
    float inv = 1.0f / fmaxf((float)(end - beg), 1.0f);
    float4 o0, o1;
    o0.x = acc[0] * inv; o0.y = acc[1] * inv; o0.z = acc[2] * inv; o0.w = acc[3] * inv;
    o1.x = acc[4] * inv; o1.y = acc[5] * inv; o1.z = acc[6] * inv; o1.w = acc[7] * inv;
    float4* prow = (float4*)(g_pool + (size_t)gq * S596);
    prow[c * 2]     = o0;
    prow[c * 2 + 1] = o1;
}

// ---------------- FC head (proven form) ----------------
__global__ void k_fc1(const float* __restrict__ Wg1, const float* __restrict__ bg1,
                      const float* __restrict__ gamma, const float* __restrict__ beta) {
    int gq = blockIdx.x;
    int o = threadIdx.x;
    __shared__ float xr[C3V];
    for (int c = threadIdx.x; c < C3V; c += blockDim.x) xr[c] = g_pool[gq * S596 + c];
    __syncthreads();
    float acc = bg1[o];
    for (int k = 0; k < C3V; k++) acc += xr[k] * Wg1[k * FC1V + o];
    float inv = 1.0f / sqrtf(1.0f + 1e-5f);
    acc = gamma[o] * (acc * inv) + beta[o];
    g_fc1[gq * FC1V + o] = fmaxf(acc, 0.0f);
}

__global__ void k_fc2(const float* __restrict__ Wg2, const float* __restrict__ bg2,
                      float* __restrict__ out) {
    int gq = blockIdx.x;
    int o = threadIdx.x;
    __shared__ float xr[FC1V];
    for (int c = threadIdx.x; c < FC1V; c += blockDim.x) xr[c] = g_fc1[gq * FC1V + c];
    __syncthreads();
    if (o < OUTV) {
        float acc = bg2[o];
        for (int k = 0; k < FC1V; k++) acc += xr[k] * Wg2[k * OUTV + o];
        out[gq * OUTV + o] = 1.0f / (1.0f + expf(-acc));
    }
}

// ---------------- launch ----------------
extern "C" void kernel_launch(void* const* d_in, const int* in_sizes, int n_in,
                              void* d_out, int out_size) {
    const float* prot_x = (const float*)d_in[0];
    const int*   src    = (const int*)d_in[1];
    const int*   dst    = (const int*)d_in[2];
    const int*   batch  = (const int*)d_in[3];
    const float* W1  = (const float*)d_in[4];
    const float* b1  = (const float*)d_in[5];
    const float* W2  = (const float*)d_in[6];
    const float* b2  = (const float*)d_in[7];
    const float* Wc1 = (const float*)d_in[8];
    const float* bc1 = (const float*)d_in[9];
    const float* Wc2 = (const float*)d_in[10];
    const float* bc2 = (const float*)d_in[11];
    const float* Wc3 = (const float*)d_in[12];
    const float* bc3 = (const float*)d_in[13];
    const float* Wg1 = (const float*)d_in[14];
    const float* bg1 = (const float*)d_in[15];
    const float* Wg2 = (const float*)d_in[16];
    const float* bg2 = (const float*)d_in[17];
    const float* gamma = (const float*)d_in[18];
    const float* beta  = (const float*)d_in[19];

    float *W1p, *dinv;
    __nv_bfloat162 *X0b, *X1b, *X2b, *X3b, *PARTB;
    __nv_bfloat16 *AGGb, *W1b, *W2b2, *W3b;
    cudaGetSymbolAddress((void**)&X0b, g_X0b);
    cudaGetSymbolAddress((void**)&X1b, g_X1b);
    cudaGetSymbolAddress((void**)&X2b, g_X2b);
    cudaGetSymbolAddress((void**)&X3b, g_X3b);
    cudaGetSymbolAddress((void**)&AGGb, g_AGGb);
    cudaGetSymbolAddress((void**)&PARTB, g_partb);
    cudaGetSymbolAddress((void**)&W1p, g_W1p);
    cudaGetSymbolAddress((void**)&W1b, g_Wc1pb);
    cudaGetSymbolAddress((void**)&W2b2, g_Wc2pb);
    cudaGetSymbolAddress((void**)&W3b, g_Wc3pb);
    cudaGetSymbolAddress((void**)&dinv, g_dinv);

    const int SMF1 = F1_STAGES * (128 * ASTR_F1 + 32 * 136) * 4;  // 107520
    const int SMC  = CSTAGE * 2 * 128 * 20 * 4;                   // 81920
    cudaFuncSetAttribute(k_f1,   cudaFuncAttributeMaxDynamicSharedMemorySize, SMF1);
    cudaFuncSetAttribute(k_mmab, cudaFuncAttributeMaxDynamicSharedMemorySize, SMC);

    const int PREP_TOTAL = W1P_SZ + PB1_SZ + PB2_SZ + PB3_SZ + N_EDGES;

    // 1-3: fused pack+count, parallel scan (2 phases)
    k_prep<<<(PREP_TOTAL + 255) / 256, 256>>>(W1, Wc1, Wc2, Wc3, dst);
    k_scan1<<<30, 1024>>>();
    k_scan2<<<30, 1024>>>();

    // 4: f1 GEMM, bf16 partials (profiler window slot)
    k_f1<<<dim3(235, 1, SPLITS), 256, SMF1>>>(prot_x + AA, W1p, PARTB, N_NODES);

    // 5-6: CSR fill, fused reduce + f2 -> X0b
    k_fill<<<(N_EDGES + 255) / 256, 256>>>(src, dst);
    k_redf2<<<RED_BLOCKS * 2, 256>>>(b1, prot_x, W2, b2);

    // conv1: agg (unscaled X0b) -> bf16 AGGb(ld 20 u4); bf16 GEMM -> X1b (dinv-scaled)
    k_aggb_old<12><<<(N_NODES + 11) / 12, dim3(20, 12)>>>(
        (const uint4*)X0b, 19, (uint4*)AGGb, 20, 19);
    k_mmab<<<dim3(235, 2), 256, SMC>>>((const uint4*)AGGb, 20, (const uint4*)W1b, 20,
                                       nullptr, 0, X1b, B149,
                                       bc1, dinv, N_NODES, 160, C1V);
    // conv2
    k_aggb_s<12><<<(N_NODES + 11) / 12, dim3(20, 12)>>>(
        (const uint4*)X1b, 19, (uint4*)AGGb, 20, 19);
    k_mmab<<<dim3(235, 3), 256, SMC>>>((const uint4*)AGGb, 20, (const uint4*)W2b2, 20,
                                       nullptr, 0, X2b, B298,
                                       bc2, dinv, N_NODES, 160, C2V);
    // conv3 -> bf16 X3b
    k_aggb_s<6><<<(N_NODES + 5) / 6, dim3(40, 6)>>>(
        (const uint4*)X2b, 38, (uint4*)AGGb, 40, 38);
    k_mmab<<<dim3(235, 5), 256, SMC>>>((const uint4*)AGGb, 40, (const uint4*)W3b, 40,
                                       nullptr, 0, X3b, B596,
                                       bc3, nullptr, N_NODES, 320, C3V);

    // pool + head
    k_pool4<<<N_GRAPHS, 80>>>(batch);
    k_fc1<<<N_GRAPHS, FC1V>>>(Wg1, bg1, gamma, beta);
    k_fc2<<<N_GRAPHS, 512>>>(Wg2, bg2, (float*)d_out);
}